// round 1
// baseline (speedup 1.0000x reference)
#include <cuda_runtime.h>
#include <math.h>

#define HWSZ 16384
#define WD 128
#define NN 8
#define CCH 64
#define C3 192
#define HIDC 170
#define HID2 340
#define NHEADS 4

// ---------------- scratch (device globals; allocation is banned) ----------------
__device__ float g_ln[(size_t)NN * CCH * HWSZ];        //  33.5 MB
__device__ float g_bufA[(size_t)NN * HID2 * HWSZ];     // 178 MB (max channel count 340)
__device__ float g_bufB[(size_t)NN * C3 * HWSZ];       // 100 MB
__device__ float g_attn[NN * NHEADS * 16 * 16];        // MDTA softmaxed attention (tiny)

// ---------------- LayerNorm over channel axis ----------------
__global__ __launch_bounds__(256) void ln_kernel(const float* __restrict__ x,
                                                 const float* __restrict__ w,
                                                 const float* __restrict__ b,
                                                 float* __restrict__ out) {
    int idx = blockIdx.x * 256 + threadIdx.x;      // over NN*HWSZ
    int n = idx >> 14, hw = idx & (HWSZ - 1);
    const float* px = x + (size_t)n * CCH * HWSZ + hw;
    float v[CCH];
    float s = 0.f;
#pragma unroll
    for (int c = 0; c < CCH; c++) { v[c] = px[(size_t)c * HWSZ]; s += v[c]; }
    float mu = s * (1.f / CCH);
    float ss = 0.f;
#pragma unroll
    for (int c = 0; c < CCH; c++) { float d = v[c] - mu; ss = fmaf(d, d, ss); }
    float inv = rsqrtf(ss * (1.f / CCH) + 1e-5f);
    float* po = out + (size_t)n * CCH * HWSZ + hw;
#pragma unroll
    for (int c = 0; c < CCH; c++) po[(size_t)c * HWSZ] = (v[c] - mu) * inv * w[c] + b[c];
}

// ---------------- pointwise conv (optionally with 3 temporal taps) ----------------
// in : (n = b*4+t, KC, HWSZ)   wgt : (M, KC, TAPS)   out : (n, M, HWSZ)
template <int KC, int TAPS>
__global__ __launch_bounds__(256) void pconv_kernel(const float* __restrict__ in,
                                                    const float* __restrict__ wgt,
                                                    const float* __restrict__ bias,
                                                    const float* __restrict__ resid,
                                                    float* __restrict__ out, int M) {
    constexpr int MT = 32;
    __shared__ float wsh[KC * TAPS * MT];
    int mbase = blockIdx.y * MT;
    for (int i = threadIdx.x; i < KC * TAPS * MT; i += 256) {
        int k = i / MT;
        int m = i - k * MT;
        int oc = mbase + m;
        wsh[i] = (oc < M) ? wgt[(size_t)oc * KC * TAPS + k] : 0.f;
    }
    __syncthreads();
    int n = blockIdx.z, b = n >> 2, t = n & 3;
    int hw = blockIdx.x * 256 + threadIdx.x;
    float acc[MT];
#pragma unroll
    for (int m = 0; m < MT; m++) acc[m] = 0.f;
#pragma unroll
    for (int dt = 0; dt < TAPS; dt++) {
        int tt = t + dt - TAPS / 2;
        if (tt < 0 || tt >= 4) continue;
        const float* src = in + ((size_t)(b * 4 + tt) * KC) * HWSZ + hw;
#pragma unroll 2
        for (int ic = 0; ic < KC; ic++) {
            float xv = __ldg(src + (size_t)ic * HWSZ);
            const float4* w4 = reinterpret_cast<const float4*>(&wsh[(ic * TAPS + dt) * MT]);
#pragma unroll
            for (int m4 = 0; m4 < MT / 4; m4++) {
                float4 wv = w4[m4];
                acc[4 * m4 + 0] = fmaf(xv, wv.x, acc[4 * m4 + 0]);
                acc[4 * m4 + 1] = fmaf(xv, wv.y, acc[4 * m4 + 1]);
                acc[4 * m4 + 2] = fmaf(xv, wv.z, acc[4 * m4 + 2]);
                acc[4 * m4 + 3] = fmaf(xv, wv.w, acc[4 * m4 + 3]);
            }
        }
    }
#pragma unroll
    for (int m = 0; m < MT; m++) {
        int oc = mbase + m;
        if (oc < M) {
            size_t o = ((size_t)n * M + oc) * HWSZ + hw;
            float r = acc[m];
            if (bias) r += bias[oc];
            if (resid) r += resid[o];
            out[o] = r;
        }
    }
}

// ---------------- depthwise 3x3 (dilation parameter) ----------------
__global__ __launch_bounds__(256) void dw3x3_kernel(const float* __restrict__ in,
                                                    const float* __restrict__ w,
                                                    const float* __restrict__ bias,
                                                    float* __restrict__ out, int CH, int dil) {
    size_t idx = (size_t)blockIdx.x * 256 + threadIdx.x;
    size_t total = (size_t)NN * CH * HWSZ;
    if (idx >= total) return;
    int hw = (int)(idx & (HWSZ - 1));
    int nc = (int)(idx >> 14);
    int c = nc % CH;
    int h = hw >> 7, x = hw & 127;
    float s = bias ? bias[c] : 0.f;
    const float* src = in + (size_t)nc * HWSZ;
    const float* wc = w + c * 9;
#pragma unroll
    for (int ki = 0; ki < 3; ki++) {
        int hh = h + (ki - 1) * dil;
        if (hh < 0 || hh >= 128) continue;
#pragma unroll
        for (int kj = 0; kj < 3; kj++) {
            int ww = x + (kj - 1) * dil;
            if (ww < 0 || ww >= 128) continue;
            s = fmaf(src[hh * WD + ww], wc[ki * 3 + kj], s);
        }
    }
    out[idx] = s;
}

// ---------------- SWSA window attention ----------------
// qkv : (n, 192, HWSZ)  [q:0-63, k:64-127, v:128-191]   rpb : (225, 4)
// out : (n, 64, HWSZ)
__global__ __launch_bounds__(256) void swsa_attn_kernel(const float* __restrict__ qkv,
                                                        const float* __restrict__ rpb,
                                                        float* __restrict__ out) {
    __shared__ float ksh[NHEADS * 64 * 16];
    __shared__ float vsh[NHEADS * 64 * 16];
    __shared__ float bsh[225 * NHEADS];
    int tid = threadIdx.x;
    int head = tid >> 6, q = tid & 63;
    int n = blockIdx.x >> 8;
    int wrem = blockIdx.x & 255;
    int wi = wrem >> 4, wj = wrem & 15;
    int qi = q >> 3, qj = q & 7;
    int pix = (wi * 8 + qi) * WD + wj * 8 + qj;

    const float* bq = qkv + ((size_t)n * C3 + head * 16) * HWSZ + pix;
    const float* bk = qkv + ((size_t)n * C3 + 64 + head * 16) * HWSZ + pix;
    const float* bv = qkv + ((size_t)n * C3 + 128 + head * 16) * HWSZ + pix;
    float qr[16];
#pragma unroll
    for (int d = 0; d < 16; d++) {
        ksh[(head * 64 + q) * 16 + d] = bk[(size_t)d * HWSZ];
        vsh[(head * 64 + q) * 16 + d] = bv[(size_t)d * HWSZ];
        qr[d] = bq[(size_t)d * HWSZ] * 0.25f;   // SCALE = 16^-0.5
    }
    for (int i = tid; i < 225 * NHEADS; i += 256) bsh[i] = rpb[i];
    __syncthreads();

    float row[64];
    float mx = -1e30f;
#pragma unroll
    for (int kk = 0; kk < 64; kk++) {
        int ki = kk >> 3, kj = kk & 7;
        float s = bsh[((qi - ki + 7) * 15 + (qj - kj + 7)) * NHEADS + head];
        const float* kr = &ksh[(head * 64 + kk) * 16];
#pragma unroll
        for (int d = 0; d < 16; d++) s = fmaf(qr[d], kr[d], s);
        row[kk] = s;
        mx = fmaxf(mx, s);
    }
    float den = 0.f;
#pragma unroll
    for (int kk = 0; kk < 64; kk++) den += expf(row[kk] - mx);
    float invden = 0.25f / den;
    float acc[16];
#pragma unroll
    for (int d = 0; d < 16; d++) acc[d] = 0.f;
#pragma unroll
    for (int kk = 0; kk < 64; kk++) {
        float a = row[kk];
        float rp = fmaxf(a, 0.f);
        float f = expf(a - mx) * invden + 0.75f * rp * rp;
        const float* vr = &vsh[(head * 64 + kk) * 16];
#pragma unroll
        for (int d = 0; d < 16; d++) acc[d] = fmaf(f, vr[d], acc[d]);
    }
    float* po = out + ((size_t)n * CCH + head * 16) * HWSZ + pix;
#pragma unroll
    for (int d = 0; d < 16; d++) po[(size_t)d * HWSZ] = acc[d];
}

// ---------------- MDTA: normalized channel Gram + softmax ----------------
// qkv : (n, 192, HWSZ)   attn_out : (n, 4, 16, 16)
__global__ __launch_bounds__(256) void mdta_gram_kernel(const float* __restrict__ qkv,
                                                        const float* __restrict__ temp,
                                                        float* __restrict__ attn_out) {
    int n = blockIdx.x >> 2, head = blockIdx.x & 3;
    int c = threadIdx.x >> 4, d = threadIdx.x & 15;
    __shared__ float qsh[16 * 129];
    __shared__ float ksh2[16 * 129];
    __shared__ float gram[256];
    __shared__ float qn[16], kn[16];
    float acc = 0.f, qq = 0.f, kk2 = 0.f;
    const float* qb = qkv + ((size_t)n * C3 + head * 16) * HWSZ;
    const float* kb = qkv + ((size_t)n * C3 + 64 + head * 16) * HWSZ;
    for (int base = 0; base < HWSZ; base += 128) {
        for (int i = threadIdx.x; i < 2048; i += 256) {
            int cc = i >> 7, j = i & 127;
            qsh[cc * 129 + j] = qb[(size_t)cc * HWSZ + base + j];
            ksh2[cc * 129 + j] = kb[(size_t)cc * HWSZ + base + j];
        }
        __syncthreads();
#pragma unroll 8
        for (int j = 0; j < 128; j++) {
            float qv = qsh[c * 129 + j];
            float kv = ksh2[d * 129 + j];
            acc = fmaf(qv, kv, acc);
            if (d == 0) qq = fmaf(qv, qv, qq);
            if (c == 0) kk2 = fmaf(kv, kv, kk2);
        }
        __syncthreads();
    }
    gram[c * 16 + d] = acc;
    if (d == 0) qn[c] = sqrtf(qq);
    if (c == 0) kn[d] = sqrtf(kk2);
    __syncthreads();
    if (threadIdx.x < 16) {
        int r = threadIdx.x;
        float tp = temp[head];
        float iq = 1.f / fmaxf(qn[r], 1e-12f);
        float rowv[16];
        float mx = -1e30f;
#pragma unroll
        for (int j = 0; j < 16; j++) {
            float a = gram[r * 16 + j] * iq / fmaxf(kn[j], 1e-12f) * tp;
            rowv[j] = a;
            mx = fmaxf(mx, a);
        }
        float den = 0.f;
#pragma unroll
        for (int j = 0; j < 16; j++) { float e = expf(rowv[j] - mx); rowv[j] = e; den += e; }
        float inv = 1.f / den;
#pragma unroll
        for (int j = 0; j < 16; j++)
            attn_out[(((size_t)n * NHEADS + head) * 16 + r) * 16 + j] = rowv[j] * inv;
    }
}

// ---------------- MDTA: out = attn @ v ----------------
__global__ __launch_bounds__(256) void mdta_out_kernel(const float* __restrict__ qkv,
                                                       const float* __restrict__ attn,
                                                       float* __restrict__ out) {
    __shared__ float ash[NHEADS * 256];
    int n = blockIdx.y;
    for (int i = threadIdx.x; i < NHEADS * 256; i += 256) ash[i] = attn[(size_t)n * NHEADS * 256 + i];
    __syncthreads();
    int hw = blockIdx.x * 256 + threadIdx.x;
#pragma unroll
    for (int head = 0; head < NHEADS; head++) {
        float vv[16];
        const float* vb = qkv + ((size_t)n * C3 + 128 + head * 16) * HWSZ + hw;
#pragma unroll
        for (int d = 0; d < 16; d++) vv[d] = vb[(size_t)d * HWSZ];
#pragma unroll
        for (int c = 0; c < 16; c++) {
            float s = 0.f;
            const float* ar = &ash[(head * 16 + c) * 16];
#pragma unroll
            for (int d = 0; d < 16; d++) s = fmaf(ar[d], vv[d], s);
            out[((size_t)n * CCH + head * 16 + c) * HWSZ + hw] = s;
        }
    }
}

// ---------------- GDFN fused depthwise + gelu gate ----------------
// in : (n, 340, HWSZ)   out : (n, 170, HWSZ)
__global__ __launch_bounds__(256) void gdfn_dw_kernel(const float* __restrict__ in,
                                                      const float* __restrict__ w1,
                                                      const float* __restrict__ b1,
                                                      const float* __restrict__ w2,
                                                      const float* __restrict__ b2,
                                                      float* __restrict__ out) {
    size_t idx = (size_t)blockIdx.x * 256 + threadIdx.x;
    if (idx >= (size_t)NN * HIDC * HWSZ) return;
    int hw = (int)(idx & (HWSZ - 1));
    int nc = (int)(idx >> 14);
    int c = nc % HIDC, n = nc / HIDC;
    int h = hw >> 7, x = hw & 127;
    const float* s1 = in + ((size_t)n * HID2 + c) * HWSZ;
    const float* s2 = in + ((size_t)n * HID2 + HIDC + c) * HWSZ;
    float a = b1[c], bb = b2[c];
    const float* wc1 = w1 + c * 9;
    const float* wc2 = w2 + c * 9;
#pragma unroll
    for (int ki = 0; ki < 3; ki++) {
        int hh = h + (ki - 1);
        if (hh < 0 || hh >= 128) continue;
#pragma unroll
        for (int kj = 0; kj < 3; kj++) {
            int ww = x + (kj - 1);
            if (ww < 0 || ww >= 128) continue;
            float v1 = s1[hh * WD + ww];
            float v2 = s2[hh * WD + ww];
            a = fmaf(v1, wc1[ki * 3 + kj], a);
            bb = fmaf(v2, wc2[ki * 3 + kj], bb);
        }
    }
    float g = 0.5f * a * (1.f + erff(a * 0.70710678118654752f));
    out[idx] = g * bb;
}

// ---------------- launch ----------------
extern "C" void kernel_launch(void* const* d_in, const int* in_sizes, int n_in,
                              void* d_out, int out_size) {
    const float* x       = (const float*)d_in[0];
    const float* norm_w  = (const float*)d_in[1];
    const float* norm_b  = (const float*)d_in[2];
    const float* s_cin_w = (const float*)d_in[3];
    const float* s_cin_b = (const float*)d_in[4];
    const float* s_dw_w  = (const float*)d_in[5];
    const float* s_dw_b  = (const float*)d_in[6];
    const float* s_rpb   = (const float*)d_in[7];
    const float* s_cout_w= (const float*)d_in[8];
    const float* s_cout_b= (const float*)d_in[9];
    const float* m_qkv_w = (const float*)d_in[10];
    const float* m_dw_w  = (const float*)d_in[11];
    const float* m_proj_w= (const float*)d_in[12];
    const float* m_temp  = (const float*)d_in[13];
    const float* g_in_w  = (const float*)d_in[14];
    const float* g_in_b  = (const float*)d_in[15];
    const float* g_d1_w  = (const float*)d_in[16];
    const float* g_d1_b  = (const float*)d_in[17];
    const float* g_d2_w  = (const float*)d_in[18];
    const float* g_d2_b  = (const float*)d_in[19];
    const float* g_out_w = (const float*)d_in[20];
    const float* g_out_b = (const float*)d_in[21];
    float* xo = (float*)d_out;

    float *ln, *bufA, *bufB, *attn;
    cudaGetSymbolAddress((void**)&ln, g_ln);
    cudaGetSymbolAddress((void**)&bufA, g_bufA);
    cudaGetSymbolAddress((void**)&bufB, g_bufB);
    cudaGetSymbolAddress((void**)&attn, g_attn);

    const int ln_blocks = NN * HWSZ / 256;

    // ===== SWSA branch =====
    ln_kernel<<<ln_blocks, 256>>>(x, norm_w, norm_b, ln);
    pconv_kernel<CCH, 3><<<dim3(HWSZ / 256, (C3 + 31) / 32, NN), 256>>>(
        ln, s_cin_w, s_cin_b, nullptr, bufB, C3);
    {
        size_t total = (size_t)NN * C3 * HWSZ;
        dw3x3_kernel<<<(unsigned)((total + 255) / 256), 256>>>(bufB, s_dw_w, s_dw_b, bufA, C3, 1);
    }
    swsa_attn_kernel<<<NN * 256, 256>>>(bufA, s_rpb, ln);
    pconv_kernel<CCH, 3><<<dim3(HWSZ / 256, (CCH + 31) / 32, NN), 256>>>(
        ln, s_cout_w, s_cout_b, x, xo, CCH);

    // ===== MDTA branch =====
    ln_kernel<<<ln_blocks, 256>>>(xo, norm_w, norm_b, ln);
    pconv_kernel<CCH, 1><<<dim3(HWSZ / 256, (C3 + 31) / 32, NN), 256>>>(
        ln, m_qkv_w, nullptr, nullptr, bufB, C3);
    {
        size_t total = (size_t)NN * C3 * HWSZ;
        dw3x3_kernel<<<(unsigned)((total + 255) / 256), 256>>>(bufB, m_dw_w, nullptr, bufA, C3, 2);
    }
    mdta_gram_kernel<<<NN * NHEADS, 256>>>(bufA, m_temp, attn);
    mdta_out_kernel<<<dim3(HWSZ / 256, NN), 256>>>(bufA, attn, ln);
    pconv_kernel<CCH, 1><<<dim3(HWSZ / 256, (CCH + 31) / 32, NN), 256>>>(
        ln, m_proj_w, nullptr, xo, xo, CCH);

    // ===== GDFN branch =====
    ln_kernel<<<ln_blocks, 256>>>(xo, norm_w, norm_b, ln);
    pconv_kernel<CCH, 1><<<dim3(HWSZ / 256, (HID2 + 31) / 32, NN), 256>>>(
        ln, g_in_w, g_in_b, nullptr, bufA, HID2);
    {
        size_t total = (size_t)NN * HIDC * HWSZ;
        gdfn_dw_kernel<<<(unsigned)((total + 255) / 256), 256>>>(bufA, g_d1_w, g_d1_b, g_d2_w, g_d2_b, bufB);
    }
    pconv_kernel<HIDC, 1><<<dim3(HWSZ / 256, (CCH + 31) / 32, NN), 256>>>(
        bufB, g_out_w, g_out_b, xo, xo, CCH);
}

// round 2
// speedup vs baseline: 1.9610x; 1.9610x over previous
#include <cuda_runtime.h>
#include <math.h>

#define HWSZ 16384
#define WD 128
#define NN 8
#define CCH 64
#define C3 192
#define HIDC 170
#define HID2 340
#define NHEADS 4

// ---------------- scratch (device globals; allocation is banned) ----------------
__device__ float g_ln[(size_t)NN * CCH * HWSZ];        //  33.5 MB
__device__ float g_bufA[(size_t)NN * HID2 * HWSZ];     // 178 MB
__device__ float g_bufB[(size_t)NN * C3 * HWSZ];       // 100 MB
__device__ float g_attn[NN * NHEADS * 16 * 16];
__device__ float g_part[512 * 288];                    // MDTA gram partials

// ---------------- LayerNorm over channel axis ----------------
__global__ __launch_bounds__(256) void ln_kernel(const float* __restrict__ x,
                                                 const float* __restrict__ w,
                                                 const float* __restrict__ b,
                                                 float* __restrict__ out) {
    int idx = blockIdx.x * 256 + threadIdx.x;      // over NN*HWSZ
    int n = idx >> 14, hw = idx & (HWSZ - 1);
    const float* px = x + (size_t)n * CCH * HWSZ + hw;
    float v[CCH];
    float s = 0.f;
#pragma unroll
    for (int c = 0; c < CCH; c++) { v[c] = px[(size_t)c * HWSZ]; s += v[c]; }
    float mu = s * (1.f / CCH);
    float ss = 0.f;
#pragma unroll
    for (int c = 0; c < CCH; c++) { float d = v[c] - mu; ss = fmaf(d, d, ss); }
    float inv = rsqrtf(ss * (1.f / CCH) + 1e-5f);
    float* po = out + (size_t)n * CCH * HWSZ + hw;
#pragma unroll
    for (int c = 0; c < CCH; c++) po[(size_t)c * HWSZ] = (v[c] - mu) * inv * w[c] + b[c];
}

// ---------------- register-tiled pointwise conv GEMM ----------------
// block: 64 out-channels x 256 pixels; thread: 8m x (4+4)p. K = KC*TAPS.
template <int KC, int TAPS>
__global__ __launch_bounds__(256, 2) void pconv2(const float* __restrict__ in,
                                                 const float* __restrict__ wgt,
                                                 const float* __restrict__ bias,
                                                 const float* __restrict__ resid,
                                                 float* __restrict__ out, int M) {
    constexpr int KTOT = KC * TAPS;
    constexpr int NCHUNK = (KTOT + 15) / 16;
    __shared__ float ash[16 * 64];    // [kk][m]
    __shared__ float bsh[16 * 256];   // [kk][p]
    const int tid = threadIdx.x;
    const int mg = tid >> 5;          // 0..7
    const int pg = tid & 31;          // 0..31
    const int mbase = blockIdx.y * 64;
    const int pix0 = blockIdx.x * 256;
    const int n = blockIdx.z, b = n >> 2, t = n & 3;

    float acc[8][8];
#pragma unroll
    for (int j = 0; j < 8; j++)
#pragma unroll
        for (int e = 0; e < 8; e++) acc[j][e] = 0.f;

    for (int c0 = 0; c0 < NCHUNK; c0++) {
        const int k0 = c0 * 16;
        // weights: [kk][m], conflict-free stores (consecutive m per tid)
#pragma unroll
        for (int i = tid; i < 1024; i += 256) {
            int kk = i >> 6, m = i & 63;
            float v = 0.f;
            if (mbase + m < M && k0 + kk < KTOT)
                v = wgt[(size_t)(mbase + m) * KTOT + k0 + kk];
            ash[kk * 64 + m] = v;
        }
        // input: [kk][p], coalesced over pixels
#pragma unroll
        for (int i = tid; i < 4096; i += 256) {
            int kk = i >> 8, p = i & 255;
            int k = k0 + kk;
            float v = 0.f;
            if (k < KTOT) {
                int ic = k / TAPS;
                int dt = k - ic * TAPS;
                int tt = t + dt - TAPS / 2;
                if (tt >= 0 && tt < 4)
                    v = in[((size_t)(b * 4 + tt) * KC + ic) * HWSZ + pix0 + p];
            }
            bsh[kk * 256 + p] = v;
        }
        __syncthreads();
#pragma unroll
        for (int kk = 0; kk < 16; kk++) {
            float am[8], bp[8];
            *(float4*)&am[0] = *(const float4*)&ash[kk * 64 + mg * 8];
            *(float4*)&am[4] = *(const float4*)&ash[kk * 64 + mg * 8 + 4];
            *(float4*)&bp[0] = *(const float4*)&bsh[kk * 256 + pg * 4];
            *(float4*)&bp[4] = *(const float4*)&bsh[kk * 256 + 128 + pg * 4];
#pragma unroll
            for (int j = 0; j < 8; j++)
#pragma unroll
                for (int e = 0; e < 8; e++)
                    acc[j][e] = fmaf(am[j], bp[e], acc[j][e]);
        }
        __syncthreads();
    }
    // epilogue
#pragma unroll
    for (int j = 0; j < 8; j++) {
        int oc = mbase + mg * 8 + j;
        if (oc >= M) continue;
        float bi = bias ? bias[oc] : 0.f;
        size_t o = ((size_t)n * M + oc) * HWSZ + pix0;
#pragma unroll
        for (int half = 0; half < 2; half++) {
            size_t oo = o + half * 128 + pg * 4;
            float4 r;
            r.x = acc[j][half * 4 + 0] + bi;
            r.y = acc[j][half * 4 + 1] + bi;
            r.z = acc[j][half * 4 + 2] + bi;
            r.w = acc[j][half * 4 + 3] + bi;
            if (resid) {
                float4 rv = *(const float4*)&resid[oo];
                r.x += rv.x; r.y += rv.y; r.z += rv.z; r.w += rv.w;
            }
            *(float4*)&out[oo] = r;
        }
    }
}

// ---------------- depthwise 3x3, float4-vectorized ----------------
__device__ __forceinline__ float4 ldz4(const float* p, bool valid) {
    return valid ? *(const float4*)p : make_float4(0.f, 0.f, 0.f, 0.f);
}

template <int DIL>
__global__ __launch_bounds__(256) void dw3x3_v4(const float* __restrict__ in,
                                                const float* __restrict__ w,
                                                const float* __restrict__ bias,
                                                float* __restrict__ out, int CH) {
    size_t idx = (size_t)blockIdx.x * 256 + threadIdx.x;
    size_t tot = (size_t)NN * CH * 4096;
    if (idx >= tot) return;
    int q = (int)(idx & 4095);
    int nc = (int)(idx >> 12);
    int h = q >> 5, x4 = (q & 31) << 2;
    int c = nc % CH;
    const float* src = in + (size_t)nc * HWSZ;
    float wl[9];
#pragma unroll
    for (int i = 0; i < 9; i++) wl[i] = w[c * 9 + i];
    float bv = bias ? bias[c] : 0.f;
    float acc[4] = {bv, bv, bv, bv};
#pragma unroll
    for (int ki = 0; ki < 3; ki++) {
        int hh = h + (ki - 1) * DIL;
        if ((unsigned)hh >= 128u) continue;
        const float* row = src + hh * WD;
        float buf[12];
        *(float4*)&buf[0] = ldz4(row + x4 - 4, x4 >= 4);
        *(float4*)&buf[4] = *(const float4*)(row + x4);
        *(float4*)&buf[8] = ldz4(row + x4 + 4, x4 < 124);
#pragma unroll
        for (int kj = 0; kj < 3; kj++) {
            float wv = wl[ki * 3 + kj];
            int off = 4 + (kj - 1) * DIL;
#pragma unroll
            for (int p = 0; p < 4; p++) acc[p] = fmaf(buf[off + p], wv, acc[p]);
        }
    }
    *(float4*)&out[idx * 4] = make_float4(acc[0], acc[1], acc[2], acc[3]);
}

// ---------------- SWSA window attention (smem-staged k/v, float4) ----------------
__global__ __launch_bounds__(256) void swsa2(const float* __restrict__ qkv,
                                             const float* __restrict__ rpb,
                                             float* __restrict__ out) {
    __shared__ float ksh[64 * 64];
    __shared__ float vsh[64 * 64];
    __shared__ float bsh[900];
    const int tid = threadIdx.x;
    const int n = blockIdx.x >> 8;
    const int wrem = blockIdx.x & 255;
    const int wi = wrem >> 4, wj = wrem & 15;
    const int wbase = (wi * 8) * WD + wj * 8;
    const size_t nb = (size_t)n * C3 * HWSZ;

    // cooperative staging of K, V (float4 over window pixels)
    for (int i = tid; i < 1024; i += 256) {
        int c = i >> 4, sub = i & 15;
        int r = sub >> 1, half = sub & 1;
        int goff = wbase + r * WD + half * 4;
        int soff = c * 64 + r * 8 + half * 4;
        *(float4*)&ksh[soff] = *(const float4*)(qkv + nb + (size_t)(64 + c) * HWSZ + goff);
        *(float4*)&vsh[soff] = *(const float4*)(qkv + nb + (size_t)(128 + c) * HWSZ + goff);
    }
    for (int i = tid; i < 900; i += 256) bsh[i] = rpb[i];
    __syncthreads();

    const int head = tid >> 6, q = tid & 63;
    const int qi = q >> 3, qj = q & 7;
    const int pix = wbase + qi * WD + qj;

    // q from global (strided, small)
    float qr[16];
    const float* bq = qkv + nb + (size_t)(head * 16) * HWSZ + pix;
#pragma unroll
    for (int d = 0; d < 16; d++) qr[d] = bq[(size_t)d * HWSZ] * 0.25f;

    float row[64];
    float mx = -1e30f;
#pragma unroll
    for (int k4 = 0; k4 < 16; k4++) {
        float s0, s1, s2, s3;
        {
            int kk = k4 * 4;
            int ki0 = kk >> 3, kj0 = kk & 7;
            s0 = bsh[((qi - ki0 + 7) * 15 + (qj - (kj0 + 0) + 7)) * NHEADS + head];
            s1 = bsh[((qi - ki0 + 7) * 15 + (qj - (kj0 + 1) + 7)) * NHEADS + head];
            s2 = bsh[((qi - ki0 + 7) * 15 + (qj - (kj0 + 2) + 7)) * NHEADS + head];
            s3 = bsh[((qi - ki0 + 7) * 15 + (qj - (kj0 + 3) + 7)) * NHEADS + head];
        }
#pragma unroll
        for (int d = 0; d < 16; d++) {
            float4 kv = *(const float4*)&ksh[(head * 16 + d) * 64 + k4 * 4];
            s0 = fmaf(qr[d], kv.x, s0);
            s1 = fmaf(qr[d], kv.y, s1);
            s2 = fmaf(qr[d], kv.z, s2);
            s3 = fmaf(qr[d], kv.w, s3);
        }
        row[k4 * 4 + 0] = s0; row[k4 * 4 + 1] = s1;
        row[k4 * 4 + 2] = s2; row[k4 * 4 + 3] = s3;
        mx = fmaxf(mx, fmaxf(fmaxf(s0, s1), fmaxf(s2, s3)));
    }
    float den = 0.f;
#pragma unroll
    for (int kk = 0; kk < 64; kk++) den += __expf(row[kk] - mx);
    float invden = 0.25f / den;

    float acc[16];
#pragma unroll
    for (int d = 0; d < 16; d++) acc[d] = 0.f;
#pragma unroll
    for (int k4 = 0; k4 < 16; k4++) {
        float f[4];
#pragma unroll
        for (int e = 0; e < 4; e++) {
            float a = row[k4 * 4 + e];
            float rp = fmaxf(a, 0.f);
            f[e] = __expf(a - mx) * invden + 0.75f * rp * rp;
        }
#pragma unroll
        for (int d = 0; d < 16; d++) {
            float4 vv = *(const float4*)&vsh[(head * 16 + d) * 64 + k4 * 4];
            acc[d] = fmaf(f[0], vv.x, fmaf(f[1], vv.y, fmaf(f[2], vv.z, fmaf(f[3], vv.w, acc[d]))));
        }
    }
    // stage result into ksh (reused), then coalesced float4 store
    __syncthreads();
#pragma unroll
    for (int d = 0; d < 16; d++) ksh[(head * 16 + d) * 64 + q] = acc[d];
    __syncthreads();
    for (int i = tid; i < 1024; i += 256) {
        int c = i >> 4, sub = i & 15;
        int r = sub >> 1, half = sub & 1;
        int goff = wbase + r * WD + half * 4;
        *(float4*)(out + ((size_t)n * CCH + c) * HWSZ + goff) =
            *(const float4*)&ksh[c * 64 + r * 8 + half * 4];
    }
}

// ---------------- MDTA gram partials (split over 16 HW segments) ----------------
__global__ __launch_bounds__(256) void mdta_gram_part(const float* __restrict__ qkv,
                                                      float* __restrict__ part) {
    int blk = blockIdx.x;
    int seg = blk & 15;
    int nh = blk >> 4;
    int n = nh >> 2, head = nh & 3;
    int c = threadIdx.x >> 4, d = threadIdx.x & 15;
    __shared__ float qsh[16 * 129];
    __shared__ float ksh2[16 * 129];
    float acc = 0.f, qq = 0.f, kk2 = 0.f;
    const float* qb = qkv + ((size_t)n * C3 + head * 16) * HWSZ;
    const float* kb = qkv + ((size_t)n * C3 + 64 + head * 16) * HWSZ;
    int base0 = seg * 1024;
    for (int it = 0; it < 8; it++) {
        int base = base0 + it * 128;
        for (int i = threadIdx.x; i < 2048; i += 256) {
            int cc = i >> 7, j = i & 127;
            qsh[cc * 129 + j] = qb[(size_t)cc * HWSZ + base + j];
            ksh2[cc * 129 + j] = kb[(size_t)cc * HWSZ + base + j];
        }
        __syncthreads();
#pragma unroll 8
        for (int j = 0; j < 128; j++) {
            float qv = qsh[c * 129 + j];
            float kv = ksh2[d * 129 + j];
            acc = fmaf(qv, kv, acc);
            if (d == 0) qq = fmaf(qv, qv, qq);
            if (c == 0) kk2 = fmaf(kv, kv, kk2);
        }
        __syncthreads();
    }
    float* pb = part + (size_t)blk * 288;
    pb[c * 16 + d] = acc;
    if (d == 0) pb[256 + c] = qq;
    if (c == 0) pb[272 + d] = kk2;
}

__global__ __launch_bounds__(256) void mdta_gram_reduce(const float* __restrict__ part,
                                                        const float* __restrict__ temp,
                                                        float* __restrict__ attn_out) {
    int nh = blockIdx.x;          // 0..31
    int n = nh >> 2, head = nh & 3;
    int tid = threadIdx.x;
    __shared__ float gram[256];
    __shared__ float qn[16], kn[16];
    float g = 0.f;
    for (int s = 0; s < 16; s++) g += part[(size_t)(nh * 16 + s) * 288 + tid];
    gram[tid] = g;
    if (tid < 16) {
        float qq = 0.f;
        for (int s = 0; s < 16; s++) qq += part[(size_t)(nh * 16 + s) * 288 + 256 + tid];
        qn[tid] = sqrtf(qq);
    } else if (tid < 32) {
        float kk = 0.f;
        for (int s = 0; s < 16; s++) kk += part[(size_t)(nh * 16 + s) * 288 + 272 + (tid - 16)];
        kn[tid - 16] = sqrtf(kk);
    }
    __syncthreads();
    if (tid < 16) {
        int r = tid;
        float tp = temp[head];
        float iq = 1.f / fmaxf(qn[r], 1e-12f);
        float rowv[16];
        float mx = -1e30f;
#pragma unroll
        for (int j = 0; j < 16; j++) {
            float a = gram[r * 16 + j] * iq / fmaxf(kn[j], 1e-12f) * tp;
            rowv[j] = a;
            mx = fmaxf(mx, a);
        }
        float den = 0.f;
#pragma unroll
        for (int j = 0; j < 16; j++) { float e = __expf(rowv[j] - mx); rowv[j] = e; den += e; }
        float inv = 1.f / den;
#pragma unroll
        for (int j = 0; j < 16; j++)
            attn_out[(((size_t)n * NHEADS + head) * 16 + r) * 16 + j] = rowv[j] * inv;
    }
}

// ---------------- MDTA: out = attn @ v (float4) ----------------
__global__ __launch_bounds__(256) void mdta_out_v4(const float* __restrict__ qkv,
                                                   const float* __restrict__ attn,
                                                   float* __restrict__ out) {
    __shared__ float ash[NHEADS * 256];
    int n = blockIdx.y;
    for (int i = threadIdx.x; i < NHEADS * 256; i += 256)
        ash[i] = attn[(size_t)n * NHEADS * 256 + i];
    __syncthreads();
    int hw = (blockIdx.x * 256 + threadIdx.x) * 4;
#pragma unroll
    for (int head = 0; head < NHEADS; head++) {
        float4 vv[16];
        const float* vb = qkv + ((size_t)n * C3 + 128 + head * 16) * HWSZ + hw;
#pragma unroll
        for (int d = 0; d < 16; d++) vv[d] = *(const float4*)(vb + (size_t)d * HWSZ);
#pragma unroll
        for (int c = 0; c < 16; c++) {
            const float* ar = &ash[(head * 16 + c) * 16];
            float4 s = make_float4(0.f, 0.f, 0.f, 0.f);
#pragma unroll
            for (int d = 0; d < 16; d++) {
                float a = ar[d];
                s.x = fmaf(a, vv[d].x, s.x);
                s.y = fmaf(a, vv[d].y, s.y);
                s.z = fmaf(a, vv[d].z, s.z);
                s.w = fmaf(a, vv[d].w, s.w);
            }
            *(float4*)(out + ((size_t)n * CCH + head * 16 + c) * HWSZ + hw) = s;
        }
    }
}

// ---------------- GDFN fused depthwise + gelu gate (float4) ----------------
__global__ __launch_bounds__(256) void gdfn_dw_v4(const float* __restrict__ in,
                                                  const float* __restrict__ w1,
                                                  const float* __restrict__ b1,
                                                  const float* __restrict__ w2,
                                                  const float* __restrict__ b2,
                                                  float* __restrict__ out) {
    size_t idx = (size_t)blockIdx.x * 256 + threadIdx.x;
    size_t tot = (size_t)NN * HIDC * 4096;
    if (idx >= tot) return;
    int q = (int)(idx & 4095);
    int nc = (int)(idx >> 12);
    int c = nc % HIDC, n = nc / HIDC;
    int h = q >> 5, x4 = (q & 31) << 2;
    const float* s1 = in + ((size_t)n * HID2 + c) * HWSZ;
    const float* s2 = s1 + (size_t)HIDC * HWSZ;
    float w1l[9], w2l[9];
#pragma unroll
    for (int i = 0; i < 9; i++) { w1l[i] = w1[c * 9 + i]; w2l[i] = w2[c * 9 + i]; }
    float bva = b1[c], bvb = b2[c];
    float a[4] = {bva, bva, bva, bva};
    float bb[4] = {bvb, bvb, bvb, bvb};
#pragma unroll
    for (int ki = 0; ki < 3; ki++) {
        int hh = h + (ki - 1);
        if ((unsigned)hh >= 128u) continue;
        const float* r1 = s1 + hh * WD;
        const float* r2 = s2 + hh * WD;
        float buf1[12], buf2[12];
        *(float4*)&buf1[0] = ldz4(r1 + x4 - 4, x4 >= 4);
        *(float4*)&buf1[4] = *(const float4*)(r1 + x4);
        *(float4*)&buf1[8] = ldz4(r1 + x4 + 4, x4 < 124);
        *(float4*)&buf2[0] = ldz4(r2 + x4 - 4, x4 >= 4);
        *(float4*)&buf2[4] = *(const float4*)(r2 + x4);
        *(float4*)&buf2[8] = ldz4(r2 + x4 + 4, x4 < 124);
#pragma unroll
        for (int kj = 0; kj < 3; kj++) {
            float wv1 = w1l[ki * 3 + kj];
            float wv2 = w2l[ki * 3 + kj];
            int off = 4 + (kj - 1);
#pragma unroll
            for (int p = 0; p < 4; p++) {
                a[p] = fmaf(buf1[off + p], wv1, a[p]);
                bb[p] = fmaf(buf2[off + p], wv2, bb[p]);
            }
        }
    }
    float4 r;
    float* rp = &r.x;
#pragma unroll
    for (int p = 0; p < 4; p++) {
        float g = 0.5f * a[p] * (1.f + erff(a[p] * 0.70710678118654752f));
        rp[p] = g * bb[p];
    }
    *(float4*)&out[idx * 4] = r;
}

// ---------------- launch ----------------
extern "C" void kernel_launch(void* const* d_in, const int* in_sizes, int n_in,
                              void* d_out, int out_size) {
    const float* x       = (const float*)d_in[0];
    const float* norm_w  = (const float*)d_in[1];
    const float* norm_b  = (const float*)d_in[2];
    const float* s_cin_w = (const float*)d_in[3];
    const float* s_cin_b = (const float*)d_in[4];
    const float* s_dw_w  = (const float*)d_in[5];
    const float* s_dw_b  = (const float*)d_in[6];
    const float* s_rpb   = (const float*)d_in[7];
    const float* s_cout_w= (const float*)d_in[8];
    const float* s_cout_b= (const float*)d_in[9];
    const float* m_qkv_w = (const float*)d_in[10];
    const float* m_dw_w  = (const float*)d_in[11];
    const float* m_proj_w= (const float*)d_in[12];
    const float* m_temp  = (const float*)d_in[13];
    const float* g_in_w  = (const float*)d_in[14];
    const float* g_in_b  = (const float*)d_in[15];
    const float* g_d1_w  = (const float*)d_in[16];
    const float* g_d1_b  = (const float*)d_in[17];
    const float* g_d2_w  = (const float*)d_in[18];
    const float* g_d2_b  = (const float*)d_in[19];
    const float* g_out_w = (const float*)d_in[20];
    const float* g_out_b = (const float*)d_in[21];
    float* xo = (float*)d_out;

    float *ln, *bufA, *bufB, *attn, *part;
    cudaGetSymbolAddress((void**)&ln, g_ln);
    cudaGetSymbolAddress((void**)&bufA, g_bufA);
    cudaGetSymbolAddress((void**)&bufB, g_bufB);
    cudaGetSymbolAddress((void**)&attn, g_attn);
    cudaGetSymbolAddress((void**)&part, g_part);

    const int ln_blocks = NN * HWSZ / 256;

    // ===== SWSA branch =====
    ln_kernel<<<ln_blocks, 256>>>(x, norm_w, norm_b, ln);
    pconv2<CCH, 3><<<dim3(64, 3, NN), 256>>>(ln, s_cin_w, s_cin_b, nullptr, bufB, C3);
    dw3x3_v4<1><<<(NN * C3 * 4096 + 255) / 256, 256>>>(bufB, s_dw_w, s_dw_b, bufA, C3);
    swsa2<<<NN * 256, 256>>>(bufA, s_rpb, ln);
    pconv2<CCH, 3><<<dim3(64, 1, NN), 256>>>(ln, s_cout_w, s_cout_b, x, xo, CCH);

    // ===== MDTA branch =====
    ln_kernel<<<ln_blocks, 256>>>(xo, norm_w, norm_b, ln);
    pconv2<CCH, 1><<<dim3(64, 3, NN), 256>>>(ln, m_qkv_w, nullptr, nullptr, bufB, C3);
    dw3x3_v4<2><<<(NN * C3 * 4096 + 255) / 256, 256>>>(bufB, m_dw_w, nullptr, bufA, C3);
    mdta_gram_part<<<512, 256>>>(bufA, part);
    mdta_gram_reduce<<<32, 256>>>(part, m_temp, attn);
    mdta_out_v4<<<dim3(16, NN), 256>>>(bufA, attn, ln);
    pconv2<CCH, 1><<<dim3(64, 1, NN), 256>>>(ln, m_proj_w, nullptr, xo, xo, CCH);

    // ===== GDFN branch =====
    ln_kernel<<<ln_blocks, 256>>>(xo, norm_w, norm_b, ln);
    pconv2<CCH, 1><<<dim3(64, 6, NN), 256>>>(ln, g_in_w, g_in_b, nullptr, bufA, HID2);
    gdfn_dw_v4<<<(NN * HIDC * 4096 + 255) / 256, 256>>>(bufA, g_d1_w, g_d1_b, g_d2_w, g_d2_b, bufB);
    pconv2<HIDC, 1><<<dim3(64, 1, NN), 256>>>(bufB, g_out_w, g_out_b, xo, xo, CCH);
}

// round 4
// speedup vs baseline: 2.0200x; 1.0301x over previous
#include <cuda_runtime.h>
#include <math.h>
#include <stdint.h>

#define HWSZ 16384
#define WD 128
#define NN 8
#define CCH 64
#define C3 192
#define HIDC 170
#define HID2 340
#define NHEADS 4

// ---------------- scratch (device globals; allocation is banned) ----------------
__device__ float g_ln[(size_t)NN * CCH * HWSZ];        //  33.5 MB (branch intermediate)
__device__ float g_bufA[(size_t)NN * HID2 * HWSZ];     // 178 MB
__device__ float g_bufB[(size_t)NN * C3 * HWSZ];       // 100 MB
__device__ float g_attn[NN * NHEADS * 16 * 16];
__device__ float g_part[512 * 288];                    // MDTA gram partials
__device__ float2 g_stats[(size_t)NN * HWSZ];          // per-pixel LN (mu, inv)

// ---------------- tf32 helpers ----------------
__device__ __forceinline__ uint32_t f2tf(float v) {
    uint32_t r;
    asm("cvt.rna.tf32.f32 %0, %1;" : "=r"(r) : "f"(v));
    return r;
}
__device__ __forceinline__ void mma_tf32(float4& d,
                                         uint32_t a0, uint32_t a1, uint32_t a2, uint32_t a3,
                                         uint32_t b0, uint32_t b1) {
    asm volatile(
        "mma.sync.aligned.m16n8k8.row.col.f32.tf32.tf32.f32 "
        "{%0,%1,%2,%3}, {%4,%5,%6,%7}, {%8,%9}, {%0,%1,%2,%3};\n"
        : "+f"(d.x), "+f"(d.y), "+f"(d.z), "+f"(d.w)
        : "r"(a0), "r"(a1), "r"(a2), "r"(a3), "r"(b0), "r"(b1));
}

// ---------------- per-pixel LayerNorm stats ----------------
__global__ __launch_bounds__(256) void ln_stats_kernel(const float* __restrict__ x,
                                                       float2* __restrict__ stats) {
    int idx = blockIdx.x * 256 + threadIdx.x;      // over NN*HWSZ
    int n = idx >> 14, hw = idx & (HWSZ - 1);
    const float* px = x + (size_t)n * CCH * HWSZ + hw;
    float s = 0.f, ss = 0.f;
#pragma unroll
    for (int c = 0; c < CCH; c++) {
        float v = px[(size_t)c * HWSZ];
        s += v; ss = fmaf(v, v, ss);
    }
    float mu = s * (1.f / CCH);
    float var = ss * (1.f / CCH) - mu * mu;
    stats[idx] = make_float2(mu, rsqrtf(fmaxf(var, 0.f) + 1e-5f));
}

// ---------------- TF32 tensor-core pointwise conv ----------------
// block tile: 64 M x 128 P, 8 warps (4 M-groups x 2 P-groups), K-chunk 32.
template <int KC, int TAPS, bool LNF>
__global__ __launch_bounds__(256) void pconv3(const float* __restrict__ in,
                                              const float2* __restrict__ stats,
                                              const float* __restrict__ wgt,
                                              const float* __restrict__ bias,
                                              const float* __restrict__ normw,
                                              const float* __restrict__ normb,
                                              const float* __restrict__ resid,
                                              float* __restrict__ out, int M) {
    constexpr int KTOT = KC * TAPS;
    constexpr int NCHUNK = (KTOT + 31) / 32;
    __shared__ union {
        struct { uint32_t W[32 * 72]; uint32_t X[32 * 136]; } ld;
        float C[64 * 132];
    } sm;

    const int tid = threadIdx.x;
    const int lane = tid & 31, warp = tid >> 5;
    const int mw = warp & 3, pw = warp >> 2;
    const int mbase = blockIdx.y * 64;
    const int pix0 = blockIdx.x * 128;
    const int n = blockIdx.z, b = n >> 2, t = n & 3;

    float4 acc[8];
#pragma unroll
    for (int j = 0; j < 8; j++) acc[j] = make_float4(0.f, 0.f, 0.f, 0.f);

    for (int c0 = 0; c0 < NCHUNK; c0++) {
        const int k0 = c0 * 32;
        // --- stage W [kk][m] (stride 72) ---
#pragma unroll
        for (int i = tid; i < 2048; i += 256) {
            int m = i & 63, kk = i >> 6, k = k0 + kk;
            float v = 0.f;
            if (mbase + m < M && k < KTOT) v = wgt[(size_t)(mbase + m) * KTOT + k];
            sm.ld.W[kk * 72 + m] = f2tf(v);
        }
        // --- stage X [kk][p] (stride 136), float4 over p ---
#pragma unroll
        for (int v4 = tid; v4 < 1024; v4 += 256) {
            int kk = v4 >> 5, p4 = (v4 & 31) * 4;
            int k = k0 + kk;
            float4 xv = make_float4(0.f, 0.f, 0.f, 0.f);
            if (k < KTOT) {
                int ic, tt;
                if (TAPS == 1) { ic = k; tt = t; }
                else { ic = k / TAPS; tt = t + (k - ic * TAPS) - TAPS / 2; }
                if (tt >= 0 && tt < 4) {
                    xv = *(const float4*)&in[((size_t)(b * 4 + tt) * KC + ic) * HWSZ + pix0 + p4];
                    if (LNF) {
                        const float2* st = &stats[(size_t)(b * 4 + tt) * HWSZ + pix0 + p4];
                        float nw = normw[ic], nbv = normb[ic];
                        float2 s0 = st[0], s1 = st[1], s2 = st[2], s3 = st[3];
                        xv.x = fmaf((xv.x - s0.x) * s0.y, nw, nbv);
                        xv.y = fmaf((xv.y - s1.x) * s1.y, nw, nbv);
                        xv.z = fmaf((xv.z - s2.x) * s2.y, nw, nbv);
                        xv.w = fmaf((xv.w - s3.x) * s3.y, nw, nbv);
                    }
                }
            }
            uint4 u;
            u.x = f2tf(xv.x); u.y = f2tf(xv.y); u.z = f2tf(xv.z); u.w = f2tf(xv.w);
            *(uint4*)&sm.ld.X[kk * 136 + p4] = u;
        }
        __syncthreads();
        // --- compute: 4 k8 steps ---
#pragma unroll
        for (int ks = 0; ks < 4; ks++) {
            const int kb = ks * 8;
            const int r = mw * 16 + (lane >> 2);
            const int kc = kb + (lane & 3);
            uint32_t a0 = sm.ld.W[kc * 72 + r];
            uint32_t a1 = sm.ld.W[kc * 72 + r + 8];
            uint32_t a2 = sm.ld.W[(kc + 4) * 72 + r];
            uint32_t a3 = sm.ld.W[(kc + 4) * 72 + r + 8];
            const int nb0 = pw * 64 + (lane >> 2);
            const int kr = kb + (lane & 3);
#pragma unroll
            for (int j = 0; j < 8; j++) {
                uint32_t b0 = sm.ld.X[kr * 136 + nb0 + j * 8];
                uint32_t b1 = sm.ld.X[(kr + 4) * 136 + nb0 + j * 8];
                mma_tf32(acc[j], a0, a1, a2, a3, b0, b1);
            }
        }
        __syncthreads();
    }
    // --- epilogue: stage C in smem, coalesced stores ---
    {
        const int r0 = mw * 16 + (lane >> 2);
        const int cb = pw * 64 + (lane & 3) * 2;
#pragma unroll
        for (int j = 0; j < 8; j++) {
            *(float2*)&sm.C[r0 * 132 + cb + j * 8] = make_float2(acc[j].x, acc[j].y);
            *(float2*)&sm.C[(r0 + 8) * 132 + cb + j * 8] = make_float2(acc[j].z, acc[j].w);
        }
    }
    __syncthreads();
#pragma unroll
    for (int i = tid; i < 2048; i += 256) {
        int oc = i >> 5, p4 = (i & 31) * 4;
        int ocg = mbase + oc;
        if (ocg >= M) continue;
        float4 r = *(const float4*)&sm.C[oc * 132 + p4];
        float bi = bias ? bias[ocg] : 0.f;
        r.x += bi; r.y += bi; r.z += bi; r.w += bi;
        size_t o = ((size_t)n * M + ocg) * HWSZ + pix0 + p4;
        if (resid) {
            float4 rv = *(const float4*)&resid[o];
            r.x += rv.x; r.y += rv.y; r.z += rv.z; r.w += rv.w;
        }
        *(float4*)&out[o] = r;
    }
}

// ---------------- depthwise 3x3, float4-vectorized ----------------
__device__ __forceinline__ float4 ldz4(const float* p, bool valid) {
    return valid ? *(const float4*)p : make_float4(0.f, 0.f, 0.f, 0.f);
}

template <int DIL>
__global__ __launch_bounds__(256) void dw3x3_v4(const float* __restrict__ in,
                                                const float* __restrict__ w,
                                                const float* __restrict__ bias,
                                                float* __restrict__ out, int CH) {
    size_t idx = (size_t)blockIdx.x * 256 + threadIdx.x;
    size_t tot = (size_t)NN * CH * 4096;
    if (idx >= tot) return;
    int q = (int)(idx & 4095);
    int nc = (int)(idx >> 12);
    int h = q >> 5, x4 = (q & 31) << 2;
    int c = nc % CH;
    const float* src = in + (size_t)nc * HWSZ;
    float wl[9];
#pragma unroll
    for (int i = 0; i < 9; i++) wl[i] = w[c * 9 + i];
    float bv = bias ? bias[c] : 0.f;
    float acc[4] = {bv, bv, bv, bv};
#pragma unroll
    for (int ki = 0; ki < 3; ki++) {
        int hh = h + (ki - 1) * DIL;
        if ((unsigned)hh >= 128u) continue;
        const float* row = src + hh * WD;
        float buf[12];
        *(float4*)&buf[0] = ldz4(row + x4 - 4, x4 >= 4);
        *(float4*)&buf[4] = *(const float4*)(row + x4);
        *(float4*)&buf[8] = ldz4(row + x4 + 4, x4 < 124);
#pragma unroll
        for (int kj = 0; kj < 3; kj++) {
            float wv = wl[ki * 3 + kj];
            int off = 4 + (kj - 1) * DIL;
#pragma unroll
            for (int p = 0; p < 4; p++) acc[p] = fmaf(buf[off + p], wv, acc[p]);
        }
    }
    *(float4*)&out[idx * 4] = make_float4(acc[0], acc[1], acc[2], acc[3]);
}

// ---------------- SWSA window attention: single-pass online, no row storage ----------------
__global__ __launch_bounds__(256) void swsa3(const float* __restrict__ qkv,
                                             const float* __restrict__ rpb,
                                             float* __restrict__ out) {
    __shared__ float ksh[64 * 64];
    __shared__ float vsh[64 * 64];
    __shared__ float bsh[900];
    const int tid = threadIdx.x;
    const int n = blockIdx.x >> 8;
    const int wrem = blockIdx.x & 255;
    const int wi = wrem >> 4, wj = wrem & 15;
    const int wbase = (wi * 8) * WD + wj * 8;
    const size_t nb = (size_t)n * C3 * HWSZ;

    for (int i = tid; i < 1024; i += 256) {
        int c = i >> 4, sub = i & 15;
        int r = sub >> 1, half = sub & 1;
        int goff = wbase + r * WD + half * 4;
        int soff = c * 64 + r * 8 + half * 4;
        *(float4*)&ksh[soff] = *(const float4*)(qkv + nb + (size_t)(64 + c) * HWSZ + goff);
        *(float4*)&vsh[soff] = *(const float4*)(qkv + nb + (size_t)(128 + c) * HWSZ + goff);
    }
    for (int i = tid; i < 900; i += 256) bsh[i] = rpb[i];
    __syncthreads();

    const int head = tid >> 6, q = tid & 63;
    const int qi = q >> 3, qj = q & 7;
    const int pix = wbase + qi * WD + qj;

    float qr[16];
    const float* bq = qkv + nb + (size_t)(head * 16) * HWSZ + pix;
#pragma unroll
    for (int d = 0; d < 16; d++) qr[d] = bq[(size_t)d * HWSZ] * 0.25f;

    float den = 0.f;
    float acc_e[16], acc_r[16];
#pragma unroll
    for (int d = 0; d < 16; d++) { acc_e[d] = 0.f; acc_r[d] = 0.f; }

#pragma unroll
    for (int k4 = 0; k4 < 16; k4++) {
        float s0, s1, s2, s3;
        {
            int kk = k4 * 4;
            int ki0 = kk >> 3, kj0 = kk & 7;
            s0 = bsh[((qi - ki0 + 7) * 15 + (qj - (kj0 + 0) + 7)) * NHEADS + head];
            s1 = bsh[((qi - ki0 + 7) * 15 + (qj - (kj0 + 1) + 7)) * NHEADS + head];
            s2 = bsh[((qi - ki0 + 7) * 15 + (qj - (kj0 + 2) + 7)) * NHEADS + head];
            s3 = bsh[((qi - ki0 + 7) * 15 + (qj - (kj0 + 3) + 7)) * NHEADS + head];
        }
#pragma unroll
        for (int d = 0; d < 16; d++) {
            float4 kv = *(const float4*)&ksh[(head * 16 + d) * 64 + k4 * 4];
            s0 = fmaf(qr[d], kv.x, s0);
            s1 = fmaf(qr[d], kv.y, s1);
            s2 = fmaf(qr[d], kv.z, s2);
            s3 = fmaf(qr[d], kv.w, s3);
        }
        float e0 = __expf(s0), e1 = __expf(s1), e2 = __expf(s2), e3 = __expf(s3);
        den += (e0 + e1) + (e2 + e3);
        float r0 = fmaxf(s0, 0.f); r0 *= r0;
        float r1 = fmaxf(s1, 0.f); r1 *= r1;
        float r2 = fmaxf(s2, 0.f); r2 *= r2;
        float r3 = fmaxf(s3, 0.f); r3 *= r3;
#pragma unroll
        for (int d = 0; d < 16; d++) {
            float4 vv = *(const float4*)&vsh[(head * 16 + d) * 64 + k4 * 4];
            acc_e[d] = fmaf(e0, vv.x, fmaf(e1, vv.y, fmaf(e2, vv.z, fmaf(e3, vv.w, acc_e[d]))));
            acc_r[d] = fmaf(r0, vv.x, fmaf(r1, vv.y, fmaf(r2, vv.z, fmaf(r3, vv.w, acc_r[d]))));
        }
    }
    float wsm = 0.25f / den;
    // stage result into ksh (reused), then coalesced float4 store
    __syncthreads();
#pragma unroll
    for (int d = 0; d < 16; d++)
        ksh[(head * 16 + d) * 64 + q] = fmaf(acc_e[d], wsm, 0.75f * acc_r[d]);
    __syncthreads();
    for (int i = tid; i < 1024; i += 256) {
        int c = i >> 4, sub = i & 15;
        int r = sub >> 1, half = sub & 1;
        int goff = wbase + r * WD + half * 4;
        *(float4*)(out + ((size_t)n * CCH + c) * HWSZ + goff) =
            *(const float4*)&ksh[c * 64 + r * 8 + half * 4];
    }
}

// ---------------- MDTA gram partials (split over 16 HW segments) ----------------
__global__ __launch_bounds__(256) void mdta_gram_part(const float* __restrict__ qkv,
                                                      float* __restrict__ part) {
    int blk = blockIdx.x;
    int seg = blk & 15;
    int nh = blk >> 4;
    int n = nh >> 2, head = nh & 3;
    int c = threadIdx.x >> 4, d = threadIdx.x & 15;
    __shared__ float qsh[16 * 129];
    __shared__ float ksh2[16 * 129];
    float acc = 0.f, qq = 0.f, kk2 = 0.f;
    const float* qb = qkv + ((size_t)n * C3 + head * 16) * HWSZ;
    const float* kb = qkv + ((size_t)n * C3 + 64 + head * 16) * HWSZ;
    int base0 = seg * 1024;
    for (int it = 0; it < 8; it++) {
        int base = base0 + it * 128;
        for (int i = threadIdx.x; i < 2048; i += 256) {
            int cc = i >> 7, j = i & 127;
            qsh[cc * 129 + j] = qb[(size_t)cc * HWSZ + base + j];
            ksh2[cc * 129 + j] = kb[(size_t)cc * HWSZ + base + j];
        }
        __syncthreads();
#pragma unroll 8
        for (int j = 0; j < 128; j++) {
            float qv = qsh[c * 129 + j];
            float kv = ksh2[d * 129 + j];
            acc = fmaf(qv, kv, acc);
            if (d == 0) qq = fmaf(qv, qv, qq);
            if (c == 0) kk2 = fmaf(kv, kv, kk2);
        }
        __syncthreads();
    }
    float* pb = part + (size_t)blk * 288;
    pb[c * 16 + d] = acc;
    if (d == 0) pb[256 + c] = qq;
    if (c == 0) pb[272 + d] = kk2;
}

__global__ __launch_bounds__(256) void mdta_gram_reduce(const float* __restrict__ part,
                                                        const float* __restrict__ temp,
                                                        float* __restrict__ attn_out) {
    int nh = blockIdx.x;          // 0..31
    int n = nh >> 2, head = nh & 3;
    int tid = threadIdx.x;
    __shared__ float gram[256];
    __shared__ float qn[16], kn[16];
    float g = 0.f;
    for (int s = 0; s < 16; s++) g += part[(size_t)(nh * 16 + s) * 288 + tid];
    gram[tid] = g;
    if (tid < 16) {
        float qq = 0.f;
        for (int s = 0; s < 16; s++) qq += part[(size_t)(nh * 16 + s) * 288 + 256 + tid];
        qn[tid] = sqrtf(qq);
    } else if (tid < 32) {
        float kk = 0.f;
        for (int s = 0; s < 16; s++) kk += part[(size_t)(nh * 16 + s) * 288 + 272 + (tid - 16)];
        kn[tid - 16] = sqrtf(kk);
    }
    __syncthreads();
    if (tid < 16) {
        int r = tid;
        float tp = temp[head];
        float iq = 1.f / fmaxf(qn[r], 1e-12f);
        float rowv[16];
        float mx = -1e30f;
#pragma unroll
        for (int j = 0; j < 16; j++) {
            float a = gram[r * 16 + j] * iq / fmaxf(kn[j], 1e-12f) * tp;
            rowv[j] = a;
            mx = fmaxf(mx, a);
        }
        float den = 0.f;
#pragma unroll
        for (int j = 0; j < 16; j++) { float e = __expf(rowv[j] - mx); rowv[j] = e; den += e; }
        float inv = 1.f / den;
#pragma unroll
        for (int j = 0; j < 16; j++)
            attn_out[(((size_t)n * NHEADS + head) * 16 + r) * 16 + j] = rowv[j] * inv;
    }
}

// ---------------- MDTA: out = attn @ v (float4) ----------------
__global__ __launch_bounds__(256) void mdta_out_v4(const float* __restrict__ qkv,
                                                   const float* __restrict__ attn,
                                                   float* __restrict__ out) {
    __shared__ float ash[NHEADS * 256];
    int n = blockIdx.y;
    for (int i = threadIdx.x; i < NHEADS * 256; i += 256)
        ash[i] = attn[(size_t)n * NHEADS * 256 + i];
    __syncthreads();
    int hw = (blockIdx.x * 256 + threadIdx.x) * 4;
#pragma unroll
    for (int head = 0; head < NHEADS; head++) {
        float4 vv[16];
        const float* vb = qkv + ((size_t)n * C3 + 128 + head * 16) * HWSZ + hw;
#pragma unroll
        for (int d = 0; d < 16; d++) vv[d] = *(const float4*)(vb + (size_t)d * HWSZ);
#pragma unroll
        for (int c = 0; c < 16; c++) {
            const float* ar = &ash[(head * 16 + c) * 16];
            float4 s = make_float4(0.f, 0.f, 0.f, 0.f);
#pragma unroll
            for (int d = 0; d < 16; d++) {
                float a = ar[d];
                s.x = fmaf(a, vv[d].x, s.x);
                s.y = fmaf(a, vv[d].y, s.y);
                s.z = fmaf(a, vv[d].z, s.z);
                s.w = fmaf(a, vv[d].w, s.w);
            }
            *(float4*)(out + ((size_t)n * CCH + head * 16 + c) * HWSZ + hw) = s;
        }
    }
}

// ---------------- GDFN fused depthwise + gelu gate (float4) ----------------
__global__ __launch_bounds__(256) void gdfn_dw_v4(const float* __restrict__ in,
                                                  const float* __restrict__ w1,
                                                  const float* __restrict__ b1,
                                                  const float* __restrict__ w2,
                                                  const float* __restrict__ b2,
                                                  float* __restrict__ out) {
    size_t idx = (size_t)blockIdx.x * 256 + threadIdx.x;
    size_t tot = (size_t)NN * HIDC * 4096;
    if (idx >= tot) return;
    int q = (int)(idx & 4095);
    int nc = (int)(idx >> 12);
    int c = nc % HIDC, n = nc / HIDC;
    int h = q >> 5, x4 = (q & 31) << 2;
    const float* s1 = in + ((size_t)n * HID2 + c) * HWSZ;
    const float* s2 = s1 + (size_t)HIDC * HWSZ;
    float w1l[9], w2l[9];
#pragma unroll
    for (int i = 0; i < 9; i++) { w1l[i] = w1[c * 9 + i]; w2l[i] = w2[c * 9 + i]; }
    float bva = b1[c], bvb = b2[c];
    float a[4] = {bva, bva, bva, bva};
    float bb[4] = {bvb, bvb, bvb, bvb};
#pragma unroll
    for (int ki = 0; ki < 3; ki++) {
        int hh = h + (ki - 1);
        if ((unsigned)hh >= 128u) continue;
        const float* r1 = s1 + hh * WD;
        const float* r2 = s2 + hh * WD;
        float buf1[12], buf2[12];
        *(float4*)&buf1[0] = ldz4(r1 + x4 - 4, x4 >= 4);
        *(float4*)&buf1[4] = *(const float4*)(r1 + x4);
        *(float4*)&buf1[8] = ldz4(r1 + x4 + 4, x4 < 124);
        *(float4*)&buf2[0] = ldz4(r2 + x4 - 4, x4 >= 4);
        *(float4*)&buf2[4] = *(const float4*)(r2 + x4);
        *(float4*)&buf2[8] = ldz4(r2 + x4 + 4, x4 < 124);
#pragma unroll
        for (int kj = 0; kj < 3; kj++) {
            float wv1 = w1l[ki * 3 + kj];
            float wv2 = w2l[ki * 3 + kj];
            int off = 4 + (kj - 1);
#pragma unroll
            for (int p = 0; p < 4; p++) {
                a[p] = fmaf(buf1[off + p], wv1, a[p]);
                bb[p] = fmaf(buf2[off + p], wv2, bb[p]);
            }
        }
    }
    float4 r;
    float* rp = &r.x;
#pragma unroll
    for (int p = 0; p < 4; p++) {
        float g = 0.5f * a[p] * (1.f + erff(a[p] * 0.70710678118654752f));
        rp[p] = g * bb[p];
    }
    *(float4*)&out[idx * 4] = r;
}

// ---------------- launch ----------------
extern "C" void kernel_launch(void* const* d_in, const int* in_sizes, int n_in,
                              void* d_out, int out_size) {
    const float* x       = (const float*)d_in[0];
    const float* norm_w  = (const float*)d_in[1];
    const float* norm_b  = (const float*)d_in[2];
    const float* s_cin_w = (const float*)d_in[3];
    const float* s_cin_b = (const float*)d_in[4];
    const float* s_dw_w  = (const float*)d_in[5];
    const float* s_dw_b  = (const float*)d_in[6];
    const float* s_rpb   = (const float*)d_in[7];
    const float* s_cout_w= (const float*)d_in[8];
    const float* s_cout_b= (const float*)d_in[9];
    const float* m_qkv_w = (const float*)d_in[10];
    const float* m_dw_w  = (const float*)d_in[11];
    const float* m_proj_w= (const float*)d_in[12];
    const float* m_temp  = (const float*)d_in[13];
    const float* g_in_w  = (const float*)d_in[14];
    const float* g_in_b  = (const float*)d_in[15];
    const float* g_d1_w  = (const float*)d_in[16];
    const float* g_d1_b  = (const float*)d_in[17];
    const float* g_d2_w  = (const float*)d_in[18];
    const float* g_d2_b  = (const float*)d_in[19];
    const float* g_out_w = (const float*)d_in[20];
    const float* g_out_b = (const float*)d_in[21];
    float* xo = (float*)d_out;

    float *ln, *bufA, *bufB, *attn, *part;
    float2* stats;
    cudaGetSymbolAddress((void**)&ln, g_ln);
    cudaGetSymbolAddress((void**)&bufA, g_bufA);
    cudaGetSymbolAddress((void**)&bufB, g_bufB);
    cudaGetSymbolAddress((void**)&attn, g_attn);
    cudaGetSymbolAddress((void**)&part, g_part);
    cudaGetSymbolAddress((void**)&stats, g_stats);

    const int st_blocks = NN * HWSZ / 256;

    // ===== SWSA branch =====
    ln_stats_kernel<<<st_blocks, 256>>>(x, stats);
    pconv3<CCH, 3, true><<<dim3(128, 3, NN), 256>>>(x, stats, s_cin_w, s_cin_b,
                                                    norm_w, norm_b, nullptr, bufB, C3);
    dw3x3_v4<1><<<(NN * C3 * 4096 + 255) / 256, 256>>>(bufB, s_dw_w, s_dw_b, bufA, C3);
    swsa3<<<NN * 256, 256>>>(bufA, s_rpb, ln);
    pconv3<CCH, 3, false><<<dim3(128, 1, NN), 256>>>(ln, nullptr, s_cout_w, s_cout_b,
                                                     nullptr, nullptr, x, xo, CCH);

    // ===== MDTA branch =====
    ln_stats_kernel<<<st_blocks, 256>>>(xo, stats);
    pconv3<CCH, 1, true><<<dim3(128, 3, NN), 256>>>(xo, stats, m_qkv_w, nullptr,
                                                    norm_w, norm_b, nullptr, bufB, C3);
    dw3x3_v4<2><<<(NN * C3 * 4096 + 255) / 256, 256>>>(bufB, m_dw_w, nullptr, bufA, C3);
    mdta_gram_part<<<512, 256>>>(bufA, part);
    mdta_gram_reduce<<<32, 256>>>(part, m_temp, attn);
    mdta_out_v4<<<dim3(16, NN), 256>>>(bufA, attn, ln);
    pconv3<CCH, 1, false><<<dim3(128, 1, NN), 256>>>(ln, nullptr, m_proj_w, nullptr,
                                                     nullptr, nullptr, xo, xo, CCH);

    // ===== GDFN branch =====
    ln_stats_kernel<<<st_blocks, 256>>>(xo, stats);
    pconv3<CCH, 1, true><<<dim3(128, 6, NN), 256>>>(xo, stats, g_in_w, g_in_b,
                                                    norm_w, norm_b, nullptr, bufA, HID2);
    gdfn_dw_v4<<<(NN * HIDC * 4096 + 255) / 256, 256>>>(bufA, g_d1_w, g_d1_b, g_d2_w, g_d2_b, bufB);
    pconv3<HIDC, 1, false><<<dim3(128, 1, NN), 256>>>(bufB, nullptr, g_out_w, g_out_b,
                                                      nullptr, nullptr, xo, xo, CCH);
}

// round 5
// speedup vs baseline: 2.9039x; 1.4376x over previous
#include <cuda_runtime.h>
#include <math.h>
#include <stdint.h>

#define HWSZ 16384
#define WD 128
#define NN 8
#define CCH 64
#define C3 192
#define HIDC 170
#define HID2 340
#define NHEADS 4

// ---------------- scratch (device globals; allocation is banned) ----------------
__device__ float g_ln[(size_t)NN * CCH * HWSZ];        //  33.5 MB (LN output / branch intermediate)
__device__ float g_bufA[(size_t)NN * HID2 * HWSZ];     // 178 MB
__device__ float g_bufB[(size_t)NN * C3 * HWSZ];       // 100 MB
__device__ float g_attn[NN * NHEADS * 16 * 16];
__device__ float g_part[512 * 288];                    // MDTA gram partials

// ---------------- tf32 mma helper ----------------
__device__ __forceinline__ void mma_tf32(float4& d,
                                         uint32_t a0, uint32_t a1, uint32_t a2, uint32_t a3,
                                         uint32_t b0, uint32_t b1) {
    asm volatile(
        "mma.sync.aligned.m16n8k8.row.col.f32.tf32.tf32.f32 "
        "{%0,%1,%2,%3}, {%4,%5,%6,%7}, {%8,%9}, {%0,%1,%2,%3};\n"
        : "+f"(d.x), "+f"(d.y), "+f"(d.z), "+f"(d.w)
        : "r"(a0), "r"(a1), "r"(a2), "r"(a3), "r"(b0), "r"(b1));
}

// ---------------- full LayerNorm over channel axis ----------------
__global__ __launch_bounds__(256) void ln_kernel(const float* __restrict__ x,
                                                 const float* __restrict__ w,
                                                 const float* __restrict__ b,
                                                 float* __restrict__ out) {
    int idx = blockIdx.x * 256 + threadIdx.x;      // over NN*HWSZ
    int n = idx >> 14, hw = idx & (HWSZ - 1);
    const float* px = x + (size_t)n * CCH * HWSZ + hw;
    float v[CCH];
    float s = 0.f;
#pragma unroll
    for (int c = 0; c < CCH; c++) { v[c] = px[(size_t)c * HWSZ]; s += v[c]; }
    float mu = s * (1.f / CCH);
    float ss = 0.f;
#pragma unroll
    for (int c = 0; c < CCH; c++) { float d = v[c] - mu; ss = fmaf(d, d, ss); }
    float inv = rsqrtf(ss * (1.f / CCH) + 1e-5f);
    float* po = out + (size_t)n * CCH * HWSZ + hw;
#pragma unroll
    for (int c = 0; c < CCH; c++) po[(size_t)c * HWSZ] = (v[c] - mu) * inv * w[c] + b[c];
}

// ---------------- TF32 tensor-core pointwise conv, cp.async double-buffered ----------------
// block tile: 128 M x 128 P, 8 warps (4 M x 2 P), each warp 32M x 64P.
// K-chunk = 16, double-buffered. WCP: cp.async size for weights (16, or 8 when
// KTOT*4 is not a multiple of 16 -> row base misaligned for odd m).
template <int KC, int TAPS, int WCP>
__global__ __launch_bounds__(256, 2) void pconv4(const float* __restrict__ in,
                                                 const float* __restrict__ wgt,
                                                 const float* __restrict__ bias,
                                                 const float* __restrict__ resid,
                                                 float* __restrict__ out, int M) {
    constexpr int KTOT = KC * TAPS;
    constexpr int NCHUNK = (KTOT + 15) / 16;
    __shared__ float sX[2][16 * 136];   // [buf][kk][p] stride 136
    __shared__ float sW[2][128 * 20];   // [buf][m][kk] stride 20

    const int tid = threadIdx.x;
    const int lane = tid & 31, warp = tid >> 5;
    const int mw = warp & 3, pw = warp >> 2;
    const int mbase = blockIdx.y * 128;
    const int pix0 = blockIdx.x * 128;
    const int n = blockIdx.z, b = n >> 2, t = n & 3;

    float4 acc[2][8];
#pragma unroll
    for (int mt = 0; mt < 2; mt++)
#pragma unroll
        for (int j = 0; j < 8; j++) acc[mt][j] = make_float4(0.f, 0.f, 0.f, 0.f);

    auto stageX = [&](int c0, int bufi) {
        const int k0 = c0 * 16;
#pragma unroll
        for (int i = tid; i < 512; i += 256) {
            int kk = i >> 5, p4 = (i & 31) << 2, k = k0 + kk;
            const float* sp = in;
            int sz = 0;
            if (k < KTOT) {
                int ic, tt;
                if (TAPS == 1) { ic = k; tt = t; }
                else { ic = k / TAPS; tt = t + (k - ic * TAPS) - 1; }
                if (tt >= 0 && tt < 4) {
                    sp = &in[((size_t)(b * 4 + tt) * KC + ic) * HWSZ + pix0 + p4];
                    sz = 16;
                }
            }
            uint32_t d = (uint32_t)__cvta_generic_to_shared(&sX[bufi][kk * 136 + p4]);
            asm volatile("cp.async.cg.shared.global [%0],[%1],16,%2;\n"
                         :: "r"(d), "l"(sp), "r"(sz));
        }
    };
    auto stageW = [&](int c0, int bufi) {
        const int k0 = c0 * 16;
        if (WCP == 16) {
#pragma unroll
            for (int i = tid; i < 512; i += 256) {
                int m = i >> 2, q = i & 3, gk = k0 + q * 4;
                int rem = (KTOT - gk) * 4;
                int sz = (mbase + m < M) ? (rem > 16 ? 16 : (rem > 0 ? rem : 0)) : 0;
                const float* sp = (sz > 0) ? &wgt[(size_t)(mbase + m) * KTOT + gk] : wgt;
                uint32_t d = (uint32_t)__cvta_generic_to_shared(&sW[bufi][m * 20 + q * 4]);
                asm volatile("cp.async.cg.shared.global [%0],[%1],16,%2;\n"
                             :: "r"(d), "l"(sp), "r"(sz));
            }
        } else {
#pragma unroll
            for (int i = tid; i < 1024; i += 256) {
                int m = i >> 3, q = i & 7, gk = k0 + q * 2;
                int rem = (KTOT - gk) * 4;
                int sz = (mbase + m < M) ? (rem > 8 ? 8 : (rem > 0 ? rem : 0)) : 0;
                const float* sp = (sz > 0) ? &wgt[(size_t)(mbase + m) * KTOT + gk] : wgt;
                uint32_t d = (uint32_t)__cvta_generic_to_shared(&sW[bufi][m * 20 + q * 2]);
                asm volatile("cp.async.ca.shared.global [%0],[%1],8,%2;\n"
                             :: "r"(d), "l"(sp), "r"(sz));
            }
        }
    };

    stageX(0, 0); stageW(0, 0);
    asm volatile("cp.async.commit_group;\n");
    int buf = 0;
    for (int c = 0; c < NCHUNK; c++) {
        if (c + 1 < NCHUNK) {
            stageX(c + 1, buf ^ 1); stageW(c + 1, buf ^ 1);
            asm volatile("cp.async.commit_group;\n");
            asm volatile("cp.async.wait_group 1;\n");
        } else {
            asm volatile("cp.async.wait_group 0;\n");
        }
        __syncthreads();
        const float* X = sX[buf];
        const float* W = sW[buf];
#pragma unroll
        for (int ks = 0; ks < 2; ks++) {
            const int kc = ks * 8 + (lane & 3);
            const int ar = mw * 32 + (lane >> 2);
            uint32_t a[2][4];
#pragma unroll
            for (int mt = 0; mt < 2; mt++) {
                const float* wr = &W[(ar + mt * 16) * 20];
                a[mt][0] = __float_as_uint(wr[kc]);
                a[mt][1] = __float_as_uint(wr[8 * 20 + kc]);
                a[mt][2] = __float_as_uint(wr[kc + 4]);
                a[mt][3] = __float_as_uint(wr[8 * 20 + kc + 4]);
            }
            const int bc = pw * 64 + (lane >> 2);
            const int br = ks * 8 + (lane & 3);
#pragma unroll
            for (int j = 0; j < 8; j++) {
                uint32_t b0 = __float_as_uint(X[br * 136 + bc + j * 8]);
                uint32_t b1 = __float_as_uint(X[(br + 4) * 136 + bc + j * 8]);
                mma_tf32(acc[0][j], a[0][0], a[0][1], a[0][2], a[0][3], b0, b1);
                mma_tf32(acc[1][j], a[1][0], a[1][1], a[1][2], a[1][3], b0, b1);
            }
        }
        __syncthreads();
        buf ^= 1;
    }

    // epilogue: direct float2 stores (32B sectors per quad-row)
    const int r0 = mw * 32 + (lane >> 2);
    const int cb = pw * 64 + ((lane & 3) << 1);
#pragma unroll
    for (int mt = 0; mt < 2; mt++) {
#pragma unroll
        for (int half = 0; half < 2; half++) {
            int oc = mbase + r0 + mt * 16 + half * 8;
            if (oc >= M) continue;
            float bi = bias ? bias[oc] : 0.f;
            size_t ob = ((size_t)n * M + oc) * HWSZ + pix0 + cb;
#pragma unroll
            for (int j = 0; j < 8; j++) {
                float2 v = (half == 0)
                    ? make_float2(acc[mt][j].x + bi, acc[mt][j].y + bi)
                    : make_float2(acc[mt][j].z + bi, acc[mt][j].w + bi);
                if (resid) {
                    float2 rv = *(const float2*)&resid[ob + j * 8];
                    v.x += rv.x; v.y += rv.y;
                }
                *(float2*)&out[ob + j * 8] = v;
            }
        }
    }
}

// ---------------- depthwise 3x3, float4-vectorized ----------------
__device__ __forceinline__ float4 ldz4(const float* p, bool valid) {
    return valid ? *(const float4*)p : make_float4(0.f, 0.f, 0.f, 0.f);
}

template <int DIL>
__global__ __launch_bounds__(256) void dw3x3_v4(const float* __restrict__ in,
                                                const float* __restrict__ w,
                                                const float* __restrict__ bias,
                                                float* __restrict__ out, int CH) {
    size_t idx = (size_t)blockIdx.x * 256 + threadIdx.x;
    size_t tot = (size_t)NN * CH * 4096;
    if (idx >= tot) return;
    int q = (int)(idx & 4095);
    int nc = (int)(idx >> 12);
    int h = q >> 5, x4 = (q & 31) << 2;
    int c = nc % CH;
    const float* src = in + (size_t)nc * HWSZ;
    float wl[9];
#pragma unroll
    for (int i = 0; i < 9; i++) wl[i] = w[c * 9 + i];
    float bv = bias ? bias[c] : 0.f;
    float acc[4] = {bv, bv, bv, bv};
#pragma unroll
    for (int ki = 0; ki < 3; ki++) {
        int hh = h + (ki - 1) * DIL;
        if ((unsigned)hh >= 128u) continue;
        const float* row = src + hh * WD;
        float buf[12];
        *(float4*)&buf[0] = ldz4(row + x4 - 4, x4 >= 4);
        *(float4*)&buf[4] = *(const float4*)(row + x4);
        *(float4*)&buf[8] = ldz4(row + x4 + 4, x4 < 124);
#pragma unroll
        for (int kj = 0; kj < 3; kj++) {
            float wv = wl[ki * 3 + kj];
            int off = 4 + (kj - 1) * DIL;
#pragma unroll
            for (int p = 0; p < 4; p++) acc[p] = fmaf(buf[off + p], wv, acc[p]);
        }
    }
    *(float4*)&out[idx * 4] = make_float4(acc[0], acc[1], acc[2], acc[3]);
}

// ---------------- SWSA window attention: single-pass online, no row storage ----------------
__global__ __launch_bounds__(256) void swsa3(const float* __restrict__ qkv,
                                             const float* __restrict__ rpb,
                                             float* __restrict__ out) {
    __shared__ float ksh[64 * 64];
    __shared__ float vsh[64 * 64];
    __shared__ float bsh[900];
    const int tid = threadIdx.x;
    const int n = blockIdx.x >> 8;
    const int wrem = blockIdx.x & 255;
    const int wi = wrem >> 4, wj = wrem & 15;
    const int wbase = (wi * 8) * WD + wj * 8;
    const size_t nb = (size_t)n * C3 * HWSZ;

    for (int i = tid; i < 1024; i += 256) {
        int c = i >> 4, sub = i & 15;
        int r = sub >> 1, half = sub & 1;
        int goff = wbase + r * WD + half * 4;
        int soff = c * 64 + r * 8 + half * 4;
        *(float4*)&ksh[soff] = *(const float4*)(qkv + nb + (size_t)(64 + c) * HWSZ + goff);
        *(float4*)&vsh[soff] = *(const float4*)(qkv + nb + (size_t)(128 + c) * HWSZ + goff);
    }
    for (int i = tid; i < 900; i += 256) bsh[i] = rpb[i];
    __syncthreads();

    const int head = tid >> 6, q = tid & 63;
    const int qi = q >> 3, qj = q & 7;
    const int pix = wbase + qi * WD + qj;

    float qr[16];
    const float* bq = qkv + nb + (size_t)(head * 16) * HWSZ + pix;
#pragma unroll
    for (int d = 0; d < 16; d++) qr[d] = bq[(size_t)d * HWSZ] * 0.25f;

    float den = 0.f;
    float acc_e[16], acc_r[16];
#pragma unroll
    for (int d = 0; d < 16; d++) { acc_e[d] = 0.f; acc_r[d] = 0.f; }

#pragma unroll
    for (int k4 = 0; k4 < 16; k4++) {
        float s0, s1, s2, s3;
        {
            int kk = k4 * 4;
            int ki0 = kk >> 3, kj0 = kk & 7;
            s0 = bsh[((qi - ki0 + 7) * 15 + (qj - (kj0 + 0) + 7)) * NHEADS + head];
            s1 = bsh[((qi - ki0 + 7) * 15 + (qj - (kj0 + 1) + 7)) * NHEADS + head];
            s2 = bsh[((qi - ki0 + 7) * 15 + (qj - (kj0 + 2) + 7)) * NHEADS + head];
            s3 = bsh[((qi - ki0 + 7) * 15 + (qj - (kj0 + 3) + 7)) * NHEADS + head];
        }
#pragma unroll
        for (int d = 0; d < 16; d++) {
            float4 kv = *(const float4*)&ksh[(head * 16 + d) * 64 + k4 * 4];
            s0 = fmaf(qr[d], kv.x, s0);
            s1 = fmaf(qr[d], kv.y, s1);
            s2 = fmaf(qr[d], kv.z, s2);
            s3 = fmaf(qr[d], kv.w, s3);
        }
        float e0 = __expf(s0), e1 = __expf(s1), e2 = __expf(s2), e3 = __expf(s3);
        den += (e0 + e1) + (e2 + e3);
        float r0 = fmaxf(s0, 0.f); r0 *= r0;
        float r1 = fmaxf(s1, 0.f); r1 *= r1;
        float r2 = fmaxf(s2, 0.f); r2 *= r2;
        float r3 = fmaxf(s3, 0.f); r3 *= r3;
#pragma unroll
        for (int d = 0; d < 16; d++) {
            float4 vv = *(const float4*)&vsh[(head * 16 + d) * 64 + k4 * 4];
            acc_e[d] = fmaf(e0, vv.x, fmaf(e1, vv.y, fmaf(e2, vv.z, fmaf(e3, vv.w, acc_e[d]))));
            acc_r[d] = fmaf(r0, vv.x, fmaf(r1, vv.y, fmaf(r2, vv.z, fmaf(r3, vv.w, acc_r[d]))));
        }
    }
    float wsm = 0.25f / den;
    __syncthreads();
#pragma unroll
    for (int d = 0; d < 16; d++)
        ksh[(head * 16 + d) * 64 + q] = fmaf(acc_e[d], wsm, 0.75f * acc_r[d]);
    __syncthreads();
    for (int i = tid; i < 1024; i += 256) {
        int c = i >> 4, sub = i & 15;
        int r = sub >> 1, half = sub & 1;
        int goff = wbase + r * WD + half * 4;
        *(float4*)(out + ((size_t)n * CCH + c) * HWSZ + goff) =
            *(const float4*)&ksh[c * 64 + r * 8 + half * 4];
    }
}

// ---------------- MDTA gram partials (split over 16 HW segments) ----------------
__global__ __launch_bounds__(256) void mdta_gram_part(const float* __restrict__ qkv,
                                                      float* __restrict__ part) {
    int blk = blockIdx.x;
    int seg = blk & 15;
    int nh = blk >> 4;
    int n = nh >> 2, head = nh & 3;
    int c = threadIdx.x >> 4, d = threadIdx.x & 15;
    __shared__ float qsh[16 * 129];
    __shared__ float ksh2[16 * 129];
    float acc = 0.f, qq = 0.f, kk2 = 0.f;
    const float* qb = qkv + ((size_t)n * C3 + head * 16) * HWSZ;
    const float* kb = qkv + ((size_t)n * C3 + 64 + head * 16) * HWSZ;
    int base0 = seg * 1024;
    for (int it = 0; it < 8; it++) {
        int base = base0 + it * 128;
        for (int i = threadIdx.x; i < 2048; i += 256) {
            int cc = i >> 7, j = i & 127;
            qsh[cc * 129 + j] = qb[(size_t)cc * HWSZ + base + j];
            ksh2[cc * 129 + j] = kb[(size_t)cc * HWSZ + base + j];
        }
        __syncthreads();
#pragma unroll 8
        for (int j = 0; j < 128; j++) {
            float qv = qsh[c * 129 + j];
            float kv = ksh2[d * 129 + j];
            acc = fmaf(qv, kv, acc);
            if (d == 0) qq = fmaf(qv, qv, qq);
            if (c == 0) kk2 = fmaf(kv, kv, kk2);
        }
        __syncthreads();
    }
    float* pb = part + (size_t)blk * 288;
    pb[c * 16 + d] = acc;
    if (d == 0) pb[256 + c] = qq;
    if (c == 0) pb[272 + d] = kk2;
}

__global__ __launch_bounds__(256) void mdta_gram_reduce(const float* __restrict__ part,
                                                        const float* __restrict__ temp,
                                                        float* __restrict__ attn_out) {
    int nh = blockIdx.x;          // 0..31
    int n = nh >> 2, head = nh & 3;
    int tid = threadIdx.x;
    __shared__ float gram[256];
    __shared__ float qn[16], kn[16];
    float g = 0.f;
    for (int s = 0; s < 16; s++) g += part[(size_t)(nh * 16 + s) * 288 + tid];
    gram[tid] = g;
    if (tid < 16) {
        float qq = 0.f;
        for (int s = 0; s < 16; s++) qq += part[(size_t)(nh * 16 + s) * 288 + 256 + tid];
        qn[tid] = sqrtf(qq);
    } else if (tid < 32) {
        float kk = 0.f;
        for (int s = 0; s < 16; s++) kk += part[(size_t)(nh * 16 + s) * 288 + 272 + (tid - 16)];
        kn[tid - 16] = sqrtf(kk);
    }
    __syncthreads();
    if (tid < 16) {
        int r = tid;
        float tp = temp[head];
        float iq = 1.f / fmaxf(qn[r], 1e-12f);
        float rowv[16];
        float mx = -1e30f;
#pragma unroll
        for (int j = 0; j < 16; j++) {
            float a = gram[r * 16 + j] * iq / fmaxf(kn[j], 1e-12f) * tp;
            rowv[j] = a;
            mx = fmaxf(mx, a);
        }
        float den = 0.f;
#pragma unroll
        for (int j = 0; j < 16; j++) { float e = __expf(rowv[j] - mx); rowv[j] = e; den += e; }
        float inv = 1.f / den;
#pragma unroll
        for (int j = 0; j < 16; j++)
            attn_out[(((size_t)n * NHEADS + head) * 16 + r) * 16 + j] = rowv[j] * inv;
    }
}

// ---------------- MDTA: out = attn @ v (float4) ----------------
__global__ __launch_bounds__(256) void mdta_out_v4(const float* __restrict__ qkv,
                                                   const float* __restrict__ attn,
                                                   float* __restrict__ out) {
    __shared__ float ash[NHEADS * 256];
    int n = blockIdx.y;
    for (int i = threadIdx.x; i < NHEADS * 256; i += 256)
        ash[i] = attn[(size_t)n * NHEADS * 256 + i];
    __syncthreads();
    int hw = (blockIdx.x * 256 + threadIdx.x) * 4;
#pragma unroll
    for (int head = 0; head < NHEADS; head++) {
        float4 vv[16];
        const float* vb = qkv + ((size_t)n * C3 + 128 + head * 16) * HWSZ + hw;
#pragma unroll
        for (int d = 0; d < 16; d++) vv[d] = *(const float4*)(vb + (size_t)d * HWSZ);
#pragma unroll
        for (int c = 0; c < 16; c++) {
            const float* ar = &ash[(head * 16 + c) * 16];
            float4 s = make_float4(0.f, 0.f, 0.f, 0.f);
#pragma unroll
            for (int d = 0; d < 16; d++) {
                float a = ar[d];
                s.x = fmaf(a, vv[d].x, s.x);
                s.y = fmaf(a, vv[d].y, s.y);
                s.z = fmaf(a, vv[d].z, s.z);
                s.w = fmaf(a, vv[d].w, s.w);
            }
            *(float4*)(out + ((size_t)n * CCH + head * 16 + c) * HWSZ + hw) = s;
        }
    }
}

// ---------------- GDFN fused depthwise + gelu gate (float4) ----------------
__global__ __launch_bounds__(256) void gdfn_dw_v4(const float* __restrict__ in,
                                                  const float* __restrict__ w1,
                                                  const float* __restrict__ b1,
                                                  const float* __restrict__ w2,
                                                  const float* __restrict__ b2,
                                                  float* __restrict__ out) {
    size_t idx = (size_t)blockIdx.x * 256 + threadIdx.x;
    size_t tot = (size_t)NN * HIDC * 4096;
    if (idx >= tot) return;
    int q = (int)(idx & 4095);
    int nc = (int)(idx >> 12);
    int c = nc % HIDC, n = nc / HIDC;
    int h = q >> 5, x4 = (q & 31) << 2;
    const float* s1 = in + ((size_t)n * HID2 + c) * HWSZ;
    const float* s2 = s1 + (size_t)HIDC * HWSZ;
    float w1l[9], w2l[9];
#pragma unroll
    for (int i = 0; i < 9; i++) { w1l[i] = w1[c * 9 + i]; w2l[i] = w2[c * 9 + i]; }
    float bva = b1[c], bvb = b2[c];
    float a[4] = {bva, bva, bva, bva};
    float bb[4] = {bvb, bvb, bvb, bvb};
#pragma unroll
    for (int ki = 0; ki < 3; ki++) {
        int hh = h + (ki - 1);
        if ((unsigned)hh >= 128u) continue;
        const float* r1 = s1 + hh * WD;
        const float* r2 = s2 + hh * WD;
        float buf1[12], buf2[12];
        *(float4*)&buf1[0] = ldz4(r1 + x4 - 4, x4 >= 4);
        *(float4*)&buf1[4] = *(const float4*)(r1 + x4);
        *(float4*)&buf1[8] = ldz4(r1 + x4 + 4, x4 < 124);
        *(float4*)&buf2[0] = ldz4(r2 + x4 - 4, x4 >= 4);
        *(float4*)&buf2[4] = *(const float4*)(r2 + x4);
        *(float4*)&buf2[8] = ldz4(r2 + x4 + 4, x4 < 124);
#pragma unroll
        for (int kj = 0; kj < 3; kj++) {
            float wv1 = w1l[ki * 3 + kj];
            float wv2 = w2l[ki * 3 + kj];
            int off = 4 + (kj - 1);
#pragma unroll
            for (int p = 0; p < 4; p++) {
                a[p] = fmaf(buf1[off + p], wv1, a[p]);
                bb[p] = fmaf(buf2[off + p], wv2, bb[p]);
            }
        }
    }
    float4 r;
    float* rp = &r.x;
#pragma unroll
    for (int p = 0; p < 4; p++) {
        float g = 0.5f * a[p] * (1.f + erff(a[p] * 0.70710678118654752f));
        rp[p] = g * bb[p];
    }
    *(float4*)&out[idx * 4] = r;
}

// ---------------- launch ----------------
extern "C" void kernel_launch(void* const* d_in, const int* in_sizes, int n_in,
                              void* d_out, int out_size) {
    const float* x       = (const float*)d_in[0];
    const float* norm_w  = (const float*)d_in[1];
    const float* norm_b  = (const float*)d_in[2];
    const float* s_cin_w = (const float*)d_in[3];
    const float* s_cin_b = (const float*)d_in[4];
    const float* s_dw_w  = (const float*)d_in[5];
    const float* s_dw_b  = (const float*)d_in[6];
    const float* s_rpb   = (const float*)d_in[7];
    const float* s_cout_w= (const float*)d_in[8];
    const float* s_cout_b= (const float*)d_in[9];
    const float* m_qkv_w = (const float*)d_in[10];
    const float* m_dw_w  = (const float*)d_in[11];
    const float* m_proj_w= (const float*)d_in[12];
    const float* m_temp  = (const float*)d_in[13];
    const float* g_in_w  = (const float*)d_in[14];
    const float* g_in_b  = (const float*)d_in[15];
    const float* g_d1_w  = (const float*)d_in[16];
    const float* g_d1_b  = (const float*)d_in[17];
    const float* g_d2_w  = (const float*)d_in[18];
    const float* g_d2_b  = (const float*)d_in[19];
    const float* g_out_w = (const float*)d_in[20];
    const float* g_out_b = (const float*)d_in[21];
    float* xo = (float*)d_out;

    float *ln, *bufA, *bufB, *attn, *part;
    cudaGetSymbolAddress((void**)&ln, g_ln);
    cudaGetSymbolAddress((void**)&bufA, g_bufA);
    cudaGetSymbolAddress((void**)&bufB, g_bufB);
    cudaGetSymbolAddress((void**)&attn, g_attn);
    cudaGetSymbolAddress((void**)&part, g_part);

    const int ln_blocks = NN * HWSZ / 256;

    // ===== SWSA branch =====
    ln_kernel<<<ln_blocks, 256>>>(x, norm_w, norm_b, ln);
    pconv4<CCH, 3, 16><<<dim3(128, 2, NN), 256>>>(ln, s_cin_w, s_cin_b, nullptr, bufB, C3);
    dw3x3_v4<1><<<(NN * C3 * 4096 + 255) / 256, 256>>>(bufB, s_dw_w, s_dw_b, bufA, C3);
    swsa3<<<NN * 256, 256>>>(bufA, s_rpb, ln);
    pconv4<CCH, 3, 16><<<dim3(128, 1, NN), 256>>>(ln, s_cout_w, s_cout_b, x, xo, CCH);

    // ===== MDTA branch =====
    ln_kernel<<<ln_blocks, 256>>>(xo, norm_w, norm_b, ln);
    pconv4<CCH, 1, 16><<<dim3(128, 2, NN), 256>>>(ln, m_qkv_w, nullptr, nullptr, bufB, C3);
    dw3x3_v4<2><<<(NN * C3 * 4096 + 255) / 256, 256>>>(bufB, m_dw_w, nullptr, bufA, C3);
    mdta_gram_part<<<512, 256>>>(bufA, part);
    mdta_gram_reduce<<<32, 256>>>(part, m_temp, attn);
    mdta_out_v4<<<dim3(16, NN), 256>>>(bufA, attn, ln);
    pconv4<CCH, 1, 16><<<dim3(128, 1, NN), 256>>>(ln, m_proj_w, nullptr, xo, xo, CCH);

    // ===== GDFN branch =====
    ln_kernel<<<ln_blocks, 256>>>(xo, norm_w, norm_b, ln);
    pconv4<CCH, 1, 16><<<dim3(128, 3, NN), 256>>>(ln, g_in_w, g_in_b, nullptr, bufA, HID2);
    gdfn_dw_v4<<<(NN * HIDC * 4096 + 255) / 256, 256>>>(bufA, g_d1_w, g_d1_b, g_d2_w, g_d2_b, bufB);
    pconv4<HIDC, 1, 8><<<dim3(128, 1, NN), 256>>>(bufB, g_out_w, g_out_b, xo, xo, CCH);
}

// round 6
// speedup vs baseline: 3.4416x; 1.1851x over previous
#include <cuda_runtime.h>
#include <cuda_bf16.h>
#include <math.h>
#include <stdint.h>

#define HWSZ 16384
#define WD 128
#define NN 8
#define CCH 64
#define C3 192
#define HIDC 170
#define HID2 340
#define NHEADS 4

// ---------------- scratch (device globals; allocation is banned) ----------------
__device__ float g_ln[(size_t)NN * CCH * HWSZ];
__device__ float g_bufA[(size_t)NN * HID2 * HWSZ];
__device__ float g_bufB[(size_t)NN * C3 * HWSZ];
__device__ float g_attn[NN * NHEADS * 16 * 16];
__device__ float g_part[512 * 288];

// ---------------- mma helpers ----------------
__device__ __forceinline__ void mma_tf32(float4& d,
                                         uint32_t a0, uint32_t a1, uint32_t a2, uint32_t a3,
                                         uint32_t b0, uint32_t b1) {
    asm volatile(
        "mma.sync.aligned.m16n8k8.row.col.f32.tf32.tf32.f32 "
        "{%0,%1,%2,%3}, {%4,%5,%6,%7}, {%8,%9}, {%0,%1,%2,%3};\n"
        : "+f"(d.x), "+f"(d.y), "+f"(d.z), "+f"(d.w)
        : "r"(a0), "r"(a1), "r"(a2), "r"(a3), "r"(b0), "r"(b1));
}
__device__ __forceinline__ void mma_bf16(float4& d,
                                         uint32_t a0, uint32_t a1, uint32_t a2, uint32_t a3,
                                         uint32_t b0, uint32_t b1) {
    asm volatile(
        "mma.sync.aligned.m16n8k16.row.col.f32.bf16.bf16.f32 "
        "{%0,%1,%2,%3}, {%4,%5,%6,%7}, {%8,%9}, {%0,%1,%2,%3};\n"
        : "+f"(d.x), "+f"(d.y), "+f"(d.z), "+f"(d.w)
        : "r"(a0), "r"(a1), "r"(a2), "r"(a3), "r"(b0), "r"(b1));
}
__device__ __forceinline__ uint32_t pack_bf16(float lo, float hi) {
    __nv_bfloat162 h = __floats2bfloat162_rn(lo, hi);
    return *(uint32_t*)&h;
}
__device__ __forceinline__ uint32_t hfma2_bf(uint32_t a, uint32_t b, uint32_t c) {
    __nv_bfloat162 r = __hfma2(*(__nv_bfloat162*)&a, *(__nv_bfloat162*)&b, *(__nv_bfloat162*)&c);
    return *(uint32_t*)&r;
}

// ---------------- full LayerNorm over channel axis ----------------
__global__ __launch_bounds__(256) void ln_kernel(const float* __restrict__ x,
                                                 const float* __restrict__ w,
                                                 const float* __restrict__ b,
                                                 float* __restrict__ out) {
    int idx = blockIdx.x * 256 + threadIdx.x;
    int n = idx >> 14, hw = idx & (HWSZ - 1);
    const float* px = x + (size_t)n * CCH * HWSZ + hw;
    float v[CCH];
    float s = 0.f;
#pragma unroll
    for (int c = 0; c < CCH; c++) { v[c] = px[(size_t)c * HWSZ]; s += v[c]; }
    float mu = s * (1.f / CCH);
    float ss = 0.f;
#pragma unroll
    for (int c = 0; c < CCH; c++) { float d = v[c] - mu; ss = fmaf(d, d, ss); }
    float inv = rsqrtf(ss * (1.f / CCH) + 1e-5f);
    float* po = out + (size_t)n * CCH * HWSZ + hw;
#pragma unroll
    for (int c = 0; c < CCH; c++) po[(size_t)c * HWSZ] = (v[c] - mu) * inv * w[c] + b[c];
}

// ---------------- TF32 pointwise conv, cp.async double-buffered ----------------
// MTILE x PTILE block tile; 8 warps, each 32M x 64P.
template <int KC, int TAPS, int WCP, int MTILE>
__global__ __launch_bounds__(256, 2) void pconv4(const float* __restrict__ in,
                                                 const float* __restrict__ wgt,
                                                 const float* __restrict__ bias,
                                                 const float* __restrict__ resid,
                                                 float* __restrict__ out, int M) {
    constexpr int KTOT = KC * TAPS;
    constexpr int NCHUNK = (KTOT + 15) / 16;
    constexpr int PTILE = (MTILE == 64) ? 256 : 128;
    constexpr int XS = PTILE + 8;
    constexpr int MW = MTILE / 32;
    __shared__ float sX[2][16 * XS];
    __shared__ float sW[2][MTILE * 20];

    const int tid = threadIdx.x;
    const int lane = tid & 31, warp = tid >> 5;
    const int mw = warp % MW, pw = warp / MW;
    const int mbase = blockIdx.y * MTILE;
    const int pix0 = blockIdx.x * PTILE;
    const int n = blockIdx.z, b = n >> 2, t = n & 3;

    float4 acc[2][8];
#pragma unroll
    for (int mt = 0; mt < 2; mt++)
#pragma unroll
        for (int j = 0; j < 8; j++) acc[mt][j] = make_float4(0.f, 0.f, 0.f, 0.f);

    auto stageX = [&](int c0, int bufi) {
        const int k0 = c0 * 16;
#pragma unroll
        for (int i = tid; i < 16 * PTILE / 4; i += 256) {
            int kk = i / (PTILE / 4), p4 = (i % (PTILE / 4)) << 2, k = k0 + kk;
            const float* sp = in;
            int sz = 0;
            if (k < KTOT) {
                int ic, tt;
                if (TAPS == 1) { ic = k; tt = t; }
                else { ic = k / TAPS; tt = t + (k - ic * TAPS) - 1; }
                if (tt >= 0 && tt < 4) {
                    sp = &in[((size_t)(b * 4 + tt) * KC + ic) * HWSZ + pix0 + p4];
                    sz = 16;
                }
            }
            uint32_t d = (uint32_t)__cvta_generic_to_shared(&sX[bufi][kk * XS + p4]);
            asm volatile("cp.async.cg.shared.global [%0],[%1],16,%2;\n"
                         :: "r"(d), "l"(sp), "r"(sz));
        }
    };
    auto stageW = [&](int c0, int bufi) {
        const int k0 = c0 * 16;
        if (WCP == 16) {
#pragma unroll
            for (int i = tid; i < MTILE * 4; i += 256) {
                int m = i >> 2, q = i & 3, gk = k0 + q * 4;
                int rem = (KTOT - gk) * 4;
                int sz = (mbase + m < M) ? (rem > 16 ? 16 : (rem > 0 ? rem : 0)) : 0;
                const float* sp = (sz > 0) ? &wgt[(size_t)(mbase + m) * KTOT + gk] : wgt;
                uint32_t d = (uint32_t)__cvta_generic_to_shared(&sW[bufi][m * 20 + q * 4]);
                asm volatile("cp.async.cg.shared.global [%0],[%1],16,%2;\n"
                             :: "r"(d), "l"(sp), "r"(sz));
            }
        } else {
#pragma unroll
            for (int i = tid; i < MTILE * 8; i += 256) {
                int m = i >> 3, q = i & 7, gk = k0 + q * 2;
                int rem = (KTOT - gk) * 4;
                int sz = (mbase + m < M) ? (rem > 8 ? 8 : (rem > 0 ? rem : 0)) : 0;
                const float* sp = (sz > 0) ? &wgt[(size_t)(mbase + m) * KTOT + gk] : wgt;
                uint32_t d = (uint32_t)__cvta_generic_to_shared(&sW[bufi][m * 20 + q * 2]);
                asm volatile("cp.async.ca.shared.global [%0],[%1],8,%2;\n"
                             :: "r"(d), "l"(sp), "r"(sz));
            }
        }
    };

    stageX(0, 0); stageW(0, 0);
    asm volatile("cp.async.commit_group;\n");
    int buf = 0;
    for (int c = 0; c < NCHUNK; c++) {
        if (c + 1 < NCHUNK) {
            stageX(c + 1, buf ^ 1); stageW(c + 1, buf ^ 1);
            asm volatile("cp.async.commit_group;\n");
            asm volatile("cp.async.wait_group 1;\n");
        } else {
            asm volatile("cp.async.wait_group 0;\n");
        }
        __syncthreads();
        const float* X = sX[buf];
        const float* W = sW[buf];
#pragma unroll
        for (int ks = 0; ks < 2; ks++) {
            const int kc = ks * 8 + (lane & 3);
            const int ar = mw * 32 + (lane >> 2);
            uint32_t a[2][4];
#pragma unroll
            for (int mt = 0; mt < 2; mt++) {
                const float* wr = &W[(ar + mt * 16) * 20];
                a[mt][0] = __float_as_uint(wr[kc]);
                a[mt][1] = __float_as_uint(wr[8 * 20 + kc]);
                a[mt][2] = __float_as_uint(wr[kc + 4]);
                a[mt][3] = __float_as_uint(wr[8 * 20 + kc + 4]);
            }
            const int bc = pw * 64 + (lane >> 2);
            const int br = ks * 8 + (lane & 3);
#pragma unroll
            for (int j = 0; j < 8; j++) {
                uint32_t b0 = __float_as_uint(X[br * XS + bc + j * 8]);
                uint32_t b1 = __float_as_uint(X[(br + 4) * XS + bc + j * 8]);
                mma_tf32(acc[0][j], a[0][0], a[0][1], a[0][2], a[0][3], b0, b1);
                mma_tf32(acc[1][j], a[1][0], a[1][1], a[1][2], a[1][3], b0, b1);
            }
        }
        __syncthreads();
        buf ^= 1;
    }

    const int r0 = mw * 32 + (lane >> 2);
    const int cb = pw * 64 + ((lane & 3) << 1);
#pragma unroll
    for (int mt = 0; mt < 2; mt++) {
#pragma unroll
        for (int half = 0; half < 2; half++) {
            int oc = mbase + r0 + mt * 16 + half * 8;
            if (oc >= M) continue;
            float bi = bias ? bias[oc] : 0.f;
            size_t ob = ((size_t)n * M + oc) * HWSZ + pix0 + cb;
#pragma unroll
            for (int j = 0; j < 8; j++) {
                float2 v = (half == 0)
                    ? make_float2(acc[mt][j].x + bi, acc[mt][j].y + bi)
                    : make_float2(acc[mt][j].z + bi, acc[mt][j].w + bi);
                if (resid) {
                    float2 rv = *(const float2*)&resid[ob + j * 8];
                    v.x += rv.x; v.y += rv.y;
                }
                *(float2*)&out[ob + j * 8] = v;
            }
        }
    }
}

// ---------------- depthwise 3x3, float4-vectorized ----------------
__device__ __forceinline__ float4 ldz4(const float* p, bool valid) {
    return valid ? *(const float4*)p : make_float4(0.f, 0.f, 0.f, 0.f);
}

template <int DIL>
__global__ __launch_bounds__(256) void dw3x3_v4(const float* __restrict__ in,
                                                const float* __restrict__ w,
                                                const float* __restrict__ bias,
                                                float* __restrict__ out, int CH) {
    size_t idx = (size_t)blockIdx.x * 256 + threadIdx.x;
    size_t tot = (size_t)NN * CH * 4096;
    if (idx >= tot) return;
    int q = (int)(idx & 4095);
    int nc = (int)(idx >> 12);
    int h = q >> 5, x4 = (q & 31) << 2;
    int c = nc % CH;
    const float* src = in + (size_t)nc * HWSZ;
    float wl[9];
#pragma unroll
    for (int i = 0; i < 9; i++) wl[i] = w[c * 9 + i];
    float bv = bias ? bias[c] : 0.f;
    float acc[4] = {bv, bv, bv, bv};
#pragma unroll
    for (int ki = 0; ki < 3; ki++) {
        int hh = h + (ki - 1) * DIL;
        if ((unsigned)hh >= 128u) continue;
        const float* row = src + hh * WD;
        float buf[12];
        *(float4*)&buf[0] = ldz4(row + x4 - 4, x4 >= 4);
        *(float4*)&buf[4] = *(const float4*)(row + x4);
        *(float4*)&buf[8] = ldz4(row + x4 + 4, x4 < 124);
#pragma unroll
        for (int kj = 0; kj < 3; kj++) {
            float wv = wl[ki * 3 + kj];
            int off = 4 + (kj - 1) * DIL;
#pragma unroll
            for (int p = 0; p < 4; p++) acc[p] = fmaf(buf[off + p], wv, acc[p]);
        }
    }
    *(float4*)&out[idx * 4] = make_float4(acc[0], acc[1], acc[2], acc[3]);
}

// ---------------- SWSA window attention via tensor cores ----------------
// block = 1 window; 8 warps = 4 heads x 2 q-halves (32 q each).
// QK^T: tf32 m16n8k8.  PV: bf16 m16n8k16 with C->A fragment reuse.
__global__ __launch_bounds__(256) void swsa4(const float* __restrict__ qkv,
                                             const float* __restrict__ rpb,
                                             float* __restrict__ out) {
    __shared__ float qsh[4 * 64 * 17];     // Q [head][q][d] x0.25 ; reused as osh [c][68]
    __shared__ float kshB[4 * 16 * 68];    // K [head][d][col]
    __shared__ uint32_t vsh[4 * 32 * 17];  // V bf16x2 pairs [head][k2][d]
    __shared__ float bsh4[4 * 225];        // bias [head][225]

    const int tid = threadIdx.x;
    const int lane = tid & 31, warp = tid >> 5;
    const int n = blockIdx.x >> 8;
    const int wrem = blockIdx.x & 255;
    const int wbase = ((wrem >> 4) * 8) * WD + (wrem & 15) * 8;
    const size_t nb = (size_t)n * C3 * HWSZ;

    for (int i = tid; i < 1024; i += 256) {
        int head = i >> 8, rem = i & 255;
        int d = rem >> 4, q4 = rem & 15;
        int goff = wbase + (q4 >> 1) * WD + (q4 & 1) * 4;
        int ch = head * 16 + d;
        float4 qv = *(const float4*)(qkv + nb + (size_t)ch * HWSZ + goff);
        float4 kv = *(const float4*)(qkv + nb + (size_t)(64 + ch) * HWSZ + goff);
        float4 vv = *(const float4*)(qkv + nb + (size_t)(128 + ch) * HWSZ + goff);
        int q0 = q4 * 4;
        float* qp = &qsh[(head * 64 + q0) * 17 + d];
        qp[0] = qv.x * 0.25f; qp[17] = qv.y * 0.25f; qp[34] = qv.z * 0.25f; qp[51] = qv.w * 0.25f;
        *(float4*)&kshB[(head * 16 + d) * 68 + q0] = kv;
        vsh[(head * 32 + q4 * 2) * 17 + d] = pack_bf16(vv.x, vv.y);
        vsh[(head * 32 + q4 * 2 + 1) * 17 + d] = pack_bf16(vv.z, vv.w);
    }
    for (int i = tid; i < 900; i += 256) bsh4[(i & 3) * 225 + (i >> 2)] = rpb[i];
    __syncthreads();

    const int head = warp >> 1;
    const int qbase = (warp & 1) * 32;
    const int r = lane >> 2;
    const int l3 = lane & 3;
    const int kj2 = l3 * 2;

    // ---- QK^T ----
    float4 S[2][8];
#pragma unroll
    for (int mt = 0; mt < 2; mt++)
#pragma unroll
        for (int nt = 0; nt < 8; nt++) S[mt][nt] = make_float4(0.f, 0.f, 0.f, 0.f);
    const float* Q = &qsh[head * 64 * 17];
    const float* K = &kshB[head * 16 * 68];
#pragma unroll
    for (int kb = 0; kb < 16; kb += 8) {
        const int kc = kb + l3;
        uint32_t a[2][4];
#pragma unroll
        for (int mt = 0; mt < 2; mt++) {
            int ar = qbase + mt * 16 + r;
            a[mt][0] = __float_as_uint(Q[ar * 17 + kc]);
            a[mt][1] = __float_as_uint(Q[(ar + 8) * 17 + kc]);
            a[mt][2] = __float_as_uint(Q[ar * 17 + kc + 4]);
            a[mt][3] = __float_as_uint(Q[(ar + 8) * 17 + kc + 4]);
        }
#pragma unroll
        for (int nt = 0; nt < 8; nt++) {
            uint32_t b0 = __float_as_uint(K[(kb + l3) * 68 + nt * 8 + r]);
            uint32_t b1 = __float_as_uint(K[(kb + 4 + l3) * 68 + nt * 8 + r]);
            mma_tf32(S[0][nt], a[0][0], a[0][1], a[0][2], a[0][3], b0, b1);
            mma_tf32(S[1][nt], a[1][0], a[1][1], a[1][2], a[1][3], b0, b1);
        }
    }

    // ---- bias + exp + relu^2, packed to bf16x2 ----
    int Aq[2][2];
#pragma unroll
    for (int mt = 0; mt < 2; mt++)
#pragma unroll
        for (int rh = 0; rh < 2; rh++) {
            int q = qbase + mt * 16 + r + rh * 8;
            Aq[mt][rh] = ((q >> 3) + 7) * 15 + (q & 7) + 7;
        }
    const float* bh = &bsh4[head * 225];
    float den[2][2] = {{0.f, 0.f}, {0.f, 0.f}};
    uint32_t eb[2][8][2], ub[2][8][2];
#pragma unroll
    for (int mt = 0; mt < 2; mt++)
#pragma unroll
        for (int nt = 0; nt < 8; nt++) {
            int bc = nt * 15 + kj2;
            int i0 = Aq[mt][0] - bc;
            int i1 = Aq[mt][1] - bc;
            float4 s = S[mt][nt];
            float s0 = s.x + bh[i0], s1 = s.y + bh[i0 - 1];
            float s2 = s.z + bh[i1], s3 = s.w + bh[i1 - 1];
            float e0 = __expf(s0), e1 = __expf(s1), e2 = __expf(s2), e3 = __expf(s3);
            den[mt][0] += e0 + e1;
            den[mt][1] += e2 + e3;
            eb[mt][nt][0] = pack_bf16(e0, e1);
            eb[mt][nt][1] = pack_bf16(e2, e3);
            float u0 = fmaxf(s0, 0.f); u0 = 0.75f * u0 * u0;
            float u1 = fmaxf(s1, 0.f); u1 = 0.75f * u1 * u1;
            float u2 = fmaxf(s2, 0.f); u2 = 0.75f * u2 * u2;
            float u3 = fmaxf(s3, 0.f); u3 = 0.75f * u3 * u3;
            ub[mt][nt][0] = pack_bf16(u0, u1);
            ub[mt][nt][1] = pack_bf16(u2, u3);
        }
    uint32_t w2[2][2];
#pragma unroll
    for (int mt = 0; mt < 2; mt++)
#pragma unroll
        for (int rh = 0; rh < 2; rh++) {
            float dv = den[mt][rh];
            dv += __shfl_xor_sync(0xffffffffu, dv, 1);
            dv += __shfl_xor_sync(0xffffffffu, dv, 2);
            float wsm = 0.25f / dv;
            w2[mt][rh] = pack_bf16(wsm, wsm);
        }

    // ---- PV via bf16 mma (C fragments -> A fragments, no shuffle) ----
    float4 O[2][2];
#pragma unroll
    for (int mt = 0; mt < 2; mt++)
#pragma unroll
        for (int v = 0; v < 2; v++) O[mt][v] = make_float4(0.f, 0.f, 0.f, 0.f);
    const uint32_t* V = &vsh[head * 32 * 17];
#pragma unroll
    for (int mt = 0; mt < 2; mt++)
#pragma unroll
        for (int t = 0; t < 4; t++) {
            uint32_t a0 = hfma2_bf(eb[mt][2 * t][0], w2[mt][0], ub[mt][2 * t][0]);
            uint32_t a1 = hfma2_bf(eb[mt][2 * t][1], w2[mt][1], ub[mt][2 * t][1]);
            uint32_t a2 = hfma2_bf(eb[mt][2 * t + 1][0], w2[mt][0], ub[mt][2 * t + 1][0]);
            uint32_t a3 = hfma2_bf(eb[mt][2 * t + 1][1], w2[mt][1], ub[mt][2 * t + 1][1]);
#pragma unroll
            for (int v = 0; v < 2; v++) {
                uint32_t b0 = V[(t * 8 + l3) * 17 + v * 8 + r];
                uint32_t b1 = V[(t * 8 + 4 + l3) * 17 + v * 8 + r];
                mma_bf16(O[mt][v], a0, a1, a2, a3, b0, b1);
            }
        }

    // ---- stage output (reuse qsh as [c][68]) + coalesced store ----
    __syncthreads();
    float* osh = qsh;
#pragma unroll
    for (int mt = 0; mt < 2; mt++)
#pragma unroll
        for (int v = 0; v < 2; v++) {
            int qrow = qbase + mt * 16 + r;
            int c0 = head * 16 + v * 8 + kj2;
            osh[c0 * 68 + qrow] = O[mt][v].x;
            osh[(c0 + 1) * 68 + qrow] = O[mt][v].y;
            osh[c0 * 68 + qrow + 8] = O[mt][v].z;
            osh[(c0 + 1) * 68 + qrow + 8] = O[mt][v].w;
        }
    __syncthreads();
    for (int i = tid; i < 1024; i += 256) {
        int c = i >> 4, sub = i & 15;
        int rr = sub >> 1, half = sub & 1;
        int goff = wbase + rr * WD + half * 4;
        *(float4*)(out + ((size_t)n * CCH + c) * HWSZ + goff) =
            *(const float4*)&osh[c * 68 + rr * 8 + half * 4];
    }
}

// ---------------- MDTA gram partials ----------------
__global__ __launch_bounds__(256) void mdta_gram_part(const float* __restrict__ qkv,
                                                      float* __restrict__ part) {
    int blk = blockIdx.x;
    int seg = blk & 15;
    int nh = blk >> 4;
    int n = nh >> 2, head = nh & 3;
    int c = threadIdx.x >> 4, d = threadIdx.x & 15;
    __shared__ float qsh[16 * 129];
    __shared__ float ksh2[16 * 129];
    float acc = 0.f, qq = 0.f, kk2 = 0.f;
    const float* qb = qkv + ((size_t)n * C3 + head * 16) * HWSZ;
    const float* kb = qkv + ((size_t)n * C3 + 64 + head * 16) * HWSZ;
    int base0 = seg * 1024;
    for (int it = 0; it < 8; it++) {
        int base = base0 + it * 128;
        for (int i = threadIdx.x; i < 2048; i += 256) {
            int cc = i >> 7, j = i & 127;
            qsh[cc * 129 + j] = qb[(size_t)cc * HWSZ + base + j];
            ksh2[cc * 129 + j] = kb[(size_t)cc * HWSZ + base + j];
        }
        __syncthreads();
#pragma unroll 8
        for (int j = 0; j < 128; j++) {
            float qv = qsh[c * 129 + j];
            float kv = ksh2[d * 129 + j];
            acc = fmaf(qv, kv, acc);
            if (d == 0) qq = fmaf(qv, qv, qq);
            if (c == 0) kk2 = fmaf(kv, kv, kk2);
        }
        __syncthreads();
    }
    float* pb = part + (size_t)blk * 288;
    pb[c * 16 + d] = acc;
    if (d == 0) pb[256 + c] = qq;
    if (c == 0) pb[272 + d] = kk2;
}

__global__ __launch_bounds__(256) void mdta_gram_reduce(const float* __restrict__ part,
                                                        const float* __restrict__ temp,
                                                        float* __restrict__ attn_out) {
    int nh = blockIdx.x;
    int n = nh >> 2, head = nh & 3;
    int tid = threadIdx.x;
    __shared__ float gram[256];
    __shared__ float qn[16], kn[16];
    float g = 0.f;
    for (int s = 0; s < 16; s++) g += part[(size_t)(nh * 16 + s) * 288 + tid];
    gram[tid] = g;
    if (tid < 16) {
        float qq = 0.f;
        for (int s = 0; s < 16; s++) qq += part[(size_t)(nh * 16 + s) * 288 + 256 + tid];
        qn[tid] = sqrtf(qq);
    } else if (tid < 32) {
        float kk = 0.f;
        for (int s = 0; s < 16; s++) kk += part[(size_t)(nh * 16 + s) * 288 + 272 + (tid - 16)];
        kn[tid - 16] = sqrtf(kk);
    }
    __syncthreads();
    if (tid < 16) {
        int r = tid;
        float tp = temp[head];
        float iq = 1.f / fmaxf(qn[r], 1e-12f);
        float rowv[16];
        float mx = -1e30f;
#pragma unroll
        for (int j = 0; j < 16; j++) {
            float a = gram[r * 16 + j] * iq / fmaxf(kn[j], 1e-12f) * tp;
            rowv[j] = a;
            mx = fmaxf(mx, a);
        }
        float den = 0.f;
#pragma unroll
        for (int j = 0; j < 16; j++) { float e = __expf(rowv[j] - mx); rowv[j] = e; den += e; }
        float inv = 1.f / den;
#pragma unroll
        for (int j = 0; j < 16; j++)
            attn_out[(((size_t)n * NHEADS + head) * 16 + r) * 16 + j] = rowv[j] * inv;
    }
}

// ---------------- MDTA: out = attn @ v (float4) ----------------
__global__ __launch_bounds__(256) void mdta_out_v4(const float* __restrict__ qkv,
                                                   const float* __restrict__ attn,
                                                   float* __restrict__ out) {
    __shared__ float ash[NHEADS * 256];
    int n = blockIdx.y;
    for (int i = threadIdx.x; i < NHEADS * 256; i += 256)
        ash[i] = attn[(size_t)n * NHEADS * 256 + i];
    __syncthreads();
    int hw = (blockIdx.x * 256 + threadIdx.x) * 4;
#pragma unroll
    for (int head = 0; head < NHEADS; head++) {
        float4 vv[16];
        const float* vb = qkv + ((size_t)n * C3 + 128 + head * 16) * HWSZ + hw;
#pragma unroll
        for (int d = 0; d < 16; d++) vv[d] = *(const float4*)(vb + (size_t)d * HWSZ);
#pragma unroll
        for (int c = 0; c < 16; c++) {
            const float* ar = &ash[(head * 16 + c) * 16];
            float4 s = make_float4(0.f, 0.f, 0.f, 0.f);
#pragma unroll
            for (int d = 0; d < 16; d++) {
                float a = ar[d];
                s.x = fmaf(a, vv[d].x, s.x);
                s.y = fmaf(a, vv[d].y, s.y);
                s.z = fmaf(a, vv[d].z, s.z);
                s.w = fmaf(a, vv[d].w, s.w);
            }
            *(float4*)(out + ((size_t)n * CCH + head * 16 + c) * HWSZ + hw) = s;
        }
    }
}

// ---------------- GDFN fused depthwise + gelu gate (float4) ----------------
__global__ __launch_bounds__(256) void gdfn_dw_v4(const float* __restrict__ in,
                                                  const float* __restrict__ w1,
                                                  const float* __restrict__ b1,
                                                  const float* __restrict__ w2,
                                                  const float* __restrict__ b2,
                                                  float* __restrict__ out) {
    size_t idx = (size_t)blockIdx.x * 256 + threadIdx.x;
    size_t tot = (size_t)NN * HIDC * 4096;
    if (idx >= tot) return;
    int q = (int)(idx & 4095);
    int nc = (int)(idx >> 12);
    int c = nc % HIDC, n = nc / HIDC;
    int h = q >> 5, x4 = (q & 31) << 2;
    const float* s1 = in + ((size_t)n * HID2 + c) * HWSZ;
    const float* s2 = s1 + (size_t)HIDC * HWSZ;
    float w1l[9], w2l[9];
#pragma unroll
    for (int i = 0; i < 9; i++) { w1l[i] = w1[c * 9 + i]; w2l[i] = w2[c * 9 + i]; }
    float bva = b1[c], bvb = b2[c];
    float a[4] = {bva, bva, bva, bva};
    float bb[4] = {bvb, bvb, bvb, bvb};
#pragma unroll
    for (int ki = 0; ki < 3; ki++) {
        int hh = h + (ki - 1);
        if ((unsigned)hh >= 128u) continue;
        const float* r1 = s1 + hh * WD;
        const float* r2 = s2 + hh * WD;
        float buf1[12], buf2[12];
        *(float4*)&buf1[0] = ldz4(r1 + x4 - 4, x4 >= 4);
        *(float4*)&buf1[4] = *(const float4*)(r1 + x4);
        *(float4*)&buf1[8] = ldz4(r1 + x4 + 4, x4 < 124);
        *(float4*)&buf2[0] = ldz4(r2 + x4 - 4, x4 >= 4);
        *(float4*)&buf2[4] = *(const float4*)(r2 + x4);
        *(float4*)&buf2[8] = ldz4(r2 + x4 + 4, x4 < 124);
#pragma unroll
        for (int kj = 0; kj < 3; kj++) {
            float wv1 = w1l[ki * 3 + kj];
            float wv2 = w2l[ki * 3 + kj];
            int off = 4 + (kj - 1);
#pragma unroll
            for (int p = 0; p < 4; p++) {
                a[p] = fmaf(buf1[off + p], wv1, a[p]);
                bb[p] = fmaf(buf2[off + p], wv2, bb[p]);
            }
        }
    }
    float4 r;
    float* rp = &r.x;
#pragma unroll
    for (int p = 0; p < 4; p++) {
        float g = 0.5f * a[p] * (1.f + erff(a[p] * 0.70710678118654752f));
        rp[p] = g * bb[p];
    }
    *(float4*)&out[idx * 4] = r;
}

// ---------------- launch ----------------
extern "C" void kernel_launch(void* const* d_in, const int* in_sizes, int n_in,
                              void* d_out, int out_size) {
    const float* x       = (const float*)d_in[0];
    const float* norm_w  = (const float*)d_in[1];
    const float* norm_b  = (const float*)d_in[2];
    const float* s_cin_w = (const float*)d_in[3];
    const float* s_cin_b = (const float*)d_in[4];
    const float* s_dw_w  = (const float*)d_in[5];
    const float* s_dw_b  = (const float*)d_in[6];
    const float* s_rpb   = (const float*)d_in[7];
    const float* s_cout_w= (const float*)d_in[8];
    const float* s_cout_b= (const float*)d_in[9];
    const float* m_qkv_w = (const float*)d_in[10];
    const float* m_dw_w  = (const float*)d_in[11];
    const float* m_proj_w= (const float*)d_in[12];
    const float* m_temp  = (const float*)d_in[13];
    const float* g_in_w  = (const float*)d_in[14];
    const float* g_in_b  = (const float*)d_in[15];
    const float* g_d1_w  = (const float*)d_in[16];
    const float* g_d1_b  = (const float*)d_in[17];
    const float* g_d2_w  = (const float*)d_in[18];
    const float* g_d2_b  = (const float*)d_in[19];
    const float* g_out_w = (const float*)d_in[20];
    const float* g_out_b = (const float*)d_in[21];
    float* xo = (float*)d_out;

    float *ln, *bufA, *bufB, *attn, *part;
    cudaGetSymbolAddress((void**)&ln, g_ln);
    cudaGetSymbolAddress((void**)&bufA, g_bufA);
    cudaGetSymbolAddress((void**)&bufB, g_bufB);
    cudaGetSymbolAddress((void**)&attn, g_attn);
    cudaGetSymbolAddress((void**)&part, g_part);

    const int ln_blocks = NN * HWSZ / 256;

    // ===== SWSA branch =====
    ln_kernel<<<ln_blocks, 256>>>(x, norm_w, norm_b, ln);
    pconv4<CCH, 3, 16, 128><<<dim3(128, 2, NN), 256>>>(ln, s_cin_w, s_cin_b, nullptr, bufB, C3);
    dw3x3_v4<1><<<(NN * C3 * 4096 + 255) / 256, 256>>>(bufB, s_dw_w, s_dw_b, bufA, C3);
    swsa4<<<NN * 256, 256>>>(bufA, s_rpb, ln);
    pconv4<CCH, 3, 16, 64><<<dim3(64, 1, NN), 256>>>(ln, s_cout_w, s_cout_b, x, xo, CCH);

    // ===== MDTA branch =====
    ln_kernel<<<ln_blocks, 256>>>(xo, norm_w, norm_b, ln);
    pconv4<CCH, 1, 16, 128><<<dim3(128, 2, NN), 256>>>(ln, m_qkv_w, nullptr, nullptr, bufB, C3);
    dw3x3_v4<2><<<(NN * C3 * 4096 + 255) / 256, 256>>>(bufB, m_dw_w, nullptr, bufA, C3);
    mdta_gram_part<<<512, 256>>>(bufA, part);
    mdta_gram_reduce<<<32, 256>>>(part, m_temp, attn);
    mdta_out_v4<<<dim3(16, NN), 256>>>(bufA, attn, ln);
    pconv4<CCH, 1, 16, 64><<<dim3(64, 1, NN), 256>>>(ln, m_proj_w, nullptr, xo, xo, CCH);

    // ===== GDFN branch =====
    ln_kernel<<<ln_blocks, 256>>>(xo, norm_w, norm_b, ln);
    pconv4<CCH, 1, 16, 128><<<dim3(128, 3, NN), 256>>>(ln, g_in_w, g_in_b, nullptr, bufA, HID2);
    gdfn_dw_v4<<<(NN * HIDC * 4096 + 255) / 256, 256>>>(bufA, g_d1_w, g_d1_b, g_d2_w, g_d2_b, bufB);
    pconv4<HIDC, 1, 8, 64><<<dim3(64, 1, NN), 256>>>(bufB, g_out_w, g_out_b, xo, xo, CCH);
}

// round 8
// speedup vs baseline: 4.3265x; 1.2571x over previous
#include <cuda_runtime.h>
#include <cuda_bf16.h>
#include <math.h>
#include <stdint.h>

#define HWSZ 16384
#define WD 128
#define NN 8
#define CCH 64
#define C3 192
#define HIDC 170
#define HID2 340
#define NHEADS 4

// ---------------- scratch (device globals; allocation is banned) ----------------
__device__ uint32_t g_lnp[(size_t)NN * 32 * HWSZ];     // packed bf16, 64ch -> 32 rows
__device__ uint32_t g_bufAp[(size_t)NN * 170 * HWSZ];  // up to 340ch packed
__device__ uint32_t g_bufBp[(size_t)NN * 96 * HWSZ];   // up to 192ch packed
__device__ float g_attn[NN * NHEADS * 16 * 16];
__device__ float g_part[512 * 288];
__device__ uint32_t g_wp[50176];                       // packed weights, all GEMMs

// weight-pack offsets (words)
#define WP_SCIN  0
#define WP_SCOUT 18432
#define WP_MQKV  24576
#define WP_MPROJ 30720
#define WP_GIN   32768
#define WP_GOUT  43648

// ---------------- helpers ----------------
__device__ __forceinline__ void mma_tf32(float4& d,
                                         uint32_t a0, uint32_t a1, uint32_t a2, uint32_t a3,
                                         uint32_t b0, uint32_t b1) {
    asm volatile(
        "mma.sync.aligned.m16n8k8.row.col.f32.tf32.tf32.f32 "
        "{%0,%1,%2,%3}, {%4,%5,%6,%7}, {%8,%9}, {%0,%1,%2,%3};\n"
        : "+f"(d.x), "+f"(d.y), "+f"(d.z), "+f"(d.w)
        : "r"(a0), "r"(a1), "r"(a2), "r"(a3), "r"(b0), "r"(b1));
}
__device__ __forceinline__ void mma_bf16(float4& d,
                                         uint32_t a0, uint32_t a1, uint32_t a2, uint32_t a3,
                                         uint32_t b0, uint32_t b1) {
    asm volatile(
        "mma.sync.aligned.m16n8k16.row.col.f32.bf16.bf16.f32 "
        "{%0,%1,%2,%3}, {%4,%5,%6,%7}, {%8,%9}, {%0,%1,%2,%3};\n"
        : "+f"(d.x), "+f"(d.y), "+f"(d.z), "+f"(d.w)
        : "r"(a0), "r"(a1), "r"(a2), "r"(a3), "r"(b0), "r"(b1));
}
__device__ __forceinline__ uint32_t pack_bf16(float lo, float hi) {
    __nv_bfloat162 h = __floats2bfloat162_rn(lo, hi);
    return *(uint32_t*)&h;
}
__device__ __forceinline__ float2 upk(uint32_t w) {
    __nv_bfloat162 h = *(__nv_bfloat162*)&w;
    return __bfloat1622float2(h);   // .x = lo, .y = hi
}
__device__ __forceinline__ uint32_t hfma2_bf(uint32_t a, uint32_t b, uint32_t c) {
    __nv_bfloat162 r = __hfma2(*(__nv_bfloat162*)&a, *(__nv_bfloat162*)&b, *(__nv_bfloat162*)&c);
    return *(uint32_t*)&r;
}
__device__ __forceinline__ uint4 uz4(const uint32_t* p, bool valid) {
    return valid ? *(const uint4*)p : make_uint4(0u, 0u, 0u, 0u);
}

// ---------------- weight pack: fp32 -> bf16x2 k-pairs (tap-major for TAPS=3) ----------------
template <int TAPS>
__global__ void wpack_kernel(const float* __restrict__ w, uint32_t* __restrict__ dst,
                             int M, int KC2, int KP2) {
    int t = blockIdx.x * 256 + threadIdx.x;
    if (t >= M * KP2) return;
    int m = t / KP2, k2 = t % KP2;
    int KTOT2 = KC2 * TAPS;
    uint32_t v = 0;
    if (k2 < KTOT2) {
        int KCfull = KC2 * 2;
        int i0, i1;
        if (TAPS == 1) { i0 = m * KCfull + 2 * k2; i1 = i0 + 1; }
        else {
            int dt = k2 / KC2, ic2 = k2 % KC2;
            i0 = (m * KCfull + 2 * ic2) * 3 + dt;
            i1 = (m * KCfull + 2 * ic2 + 1) * 3 + dt;
        }
        v = pack_bf16(w[i0], w[i1]);
    }
    dst[t] = v;
}

// ---------------- LayerNorm -> packed bf16 ----------------
__global__ __launch_bounds__(256) void ln_p(const float* __restrict__ x,
                                            const float* __restrict__ w,
                                            const float* __restrict__ b,
                                            uint32_t* __restrict__ outp) {
    int idx = blockIdx.x * 256 + threadIdx.x;
    int n = idx >> 14, hw = idx & (HWSZ - 1);
    const float* px = x + (size_t)n * CCH * HWSZ + hw;
    float v[CCH];
    float s = 0.f;
#pragma unroll
    for (int c = 0; c < CCH; c++) { v[c] = px[(size_t)c * HWSZ]; s += v[c]; }
    float mu = s * (1.f / CCH);
    float ss = 0.f;
#pragma unroll
    for (int c = 0; c < CCH; c++) { float d = v[c] - mu; ss = fmaf(d, d, ss); }
    float inv = rsqrtf(ss * (1.f / CCH) + 1e-5f);
    uint32_t* po = outp + (size_t)n * 32 * HWSZ + hw;
#pragma unroll
    for (int c2 = 0; c2 < 32; c2++) {
        float a = (v[2 * c2] - mu) * inv * w[2 * c2] + b[2 * c2];
        float c_ = (v[2 * c2 + 1] - mu) * inv * w[2 * c2 + 1] + b[2 * c2 + 1];
        po[(size_t)c2 * HWSZ] = pack_bf16(a, c_);
    }
}

// ---------------- bf16 tensor-core pointwise conv, cp.async double-buffered ----------------
// packed in [n][KC2 rows][HWSZ], packed weights [M][KP2]. K-chunk = 8 k2-rows (16 K).
template <int KC2, int TAPS, int MTILE, bool OUTBF>
__global__ __launch_bounds__(256, 2) void pconv5(const uint32_t* __restrict__ inp,
                                                 const uint32_t* __restrict__ wp,
                                                 const float* __restrict__ bias,
                                                 const float* __restrict__ resid,
                                                 float* __restrict__ outf,
                                                 uint32_t* __restrict__ outp, int M) {
    constexpr int KTOT2 = KC2 * TAPS;
    constexpr int NCHUNK = (KTOT2 + 7) / 8;
    constexpr int KP2 = NCHUNK * 8;
    constexpr int PTILE = (MTILE == 64) ? 256 : 128;
    constexpr int XSW = PTILE + 8;
    constexpr int WSW = 12;
    constexpr int MW = MTILE / 32;
    __shared__ uint32_t sX[2][8 * XSW];
    __shared__ uint32_t sW[2][MTILE * WSW];

    const int tid = threadIdx.x;
    const int lane = tid & 31, warp = tid >> 5;
    const int mw = warp % MW, pw = warp / MW;
    const int mbase = blockIdx.y * MTILE;
    const int pix0 = blockIdx.x * PTILE;
    const int n = blockIdx.z, b = n >> 2, t = n & 3;
    const int l3 = lane & 3, r = lane >> 2;

    float4 acc[2][8];
#pragma unroll
    for (int mt = 0; mt < 2; mt++)
#pragma unroll
        for (int j = 0; j < 8; j++) acc[mt][j] = make_float4(0.f, 0.f, 0.f, 0.f);

    auto stageX = [&](int c0, int bufi) {
#pragma unroll
        for (int i = tid; i < 2 * PTILE; i += 256) {
            int row = i / (PTILE / 4), p4 = (i % (PTILE / 4)) << 2;
            int k2 = c0 * 8 + row;
            const uint32_t* sp = inp;
            int sz = 0;
            if (k2 < KTOT2) {
                int ic2, tt;
                if (TAPS == 1) { ic2 = k2; tt = t; }
                else { int dt = k2 / KC2; ic2 = k2 - dt * KC2; tt = t + dt - 1; }
                if (tt >= 0 && tt < 4) {
                    sp = &inp[((size_t)(b * 4 + tt) * KC2 + ic2) * HWSZ + pix0 + p4];
                    sz = 16;
                }
            }
            uint32_t d = (uint32_t)__cvta_generic_to_shared(&sX[bufi][row * XSW + p4]);
            asm volatile("cp.async.cg.shared.global [%0],[%1],16,%2;\n"
                         :: "r"(d), "l"(sp), "r"(sz));
        }
    };
    auto stageW = [&](int c0, int bufi) {
#pragma unroll
        for (int i = tid; i < MTILE * 2; i += 256) {
            int m = i >> 1, q = i & 1;
            int gk2 = c0 * 8 + q * 4;
            int sz = (mbase + m < M) ? 16 : 0;
            const uint32_t* sp = (sz > 0) ? &wp[(size_t)(mbase + m) * KP2 + gk2] : wp;
            uint32_t d = (uint32_t)__cvta_generic_to_shared(&sW[bufi][m * WSW + q * 4]);
            asm volatile("cp.async.cg.shared.global [%0],[%1],16,%2;\n"
                         :: "r"(d), "l"(sp), "r"(sz));
        }
    };

    stageX(0, 0); stageW(0, 0);
    asm volatile("cp.async.commit_group;\n");
    int buf = 0;
    for (int c = 0; c < NCHUNK; c++) {
        if (c + 1 < NCHUNK) {
            stageX(c + 1, buf ^ 1); stageW(c + 1, buf ^ 1);
            asm volatile("cp.async.commit_group;\n");
            asm volatile("cp.async.wait_group 1;\n");
        } else {
            asm volatile("cp.async.wait_group 0;\n");
        }
        __syncthreads();
        const uint32_t* X = sX[buf];
        const uint32_t* W = sW[buf];
        const int ar = mw * 32 + r;
        uint32_t a[2][4];
#pragma unroll
        for (int mt = 0; mt < 2; mt++) {
            int wb = (ar + mt * 16) * WSW;
            a[mt][0] = W[wb + l3];
            a[mt][1] = W[wb + 8 * WSW + l3];
            a[mt][2] = W[wb + l3 + 4];
            a[mt][3] = W[wb + 8 * WSW + l3 + 4];
        }
        const int bc = pw * 64 + r;
#pragma unroll
        for (int nt = 0; nt < 8; nt++) {
            uint32_t b0 = X[l3 * XSW + bc + nt * 8];
            uint32_t b1 = X[(l3 + 4) * XSW + bc + nt * 8];
            mma_bf16(acc[0][nt], a[0][0], a[0][1], a[0][2], a[0][3], b0, b1);
            mma_bf16(acc[1][nt], a[1][0], a[1][1], a[1][2], a[1][3], b0, b1);
        }
        __syncthreads();
        buf ^= 1;
    }

    const int r0 = mw * 32 + r;
    const int cb = pw * 64 + (l3 << 1);
    if (OUTBF) {
        const int M2 = M >> 1;
#pragma unroll
        for (int mt = 0; mt < 2; mt++)
#pragma unroll
            for (int half = 0; half < 2; half++) {
                int oc = mbase + r0 + mt * 16 + half * 8;
                float bi = (bias && oc < M) ? bias[oc] : 0.f;
#pragma unroll
                for (int j = 0; j < 8; j++) {
                    float vx = (half ? acc[mt][j].z : acc[mt][j].x) + bi;
                    float vy = (half ? acc[mt][j].w : acc[mt][j].y) + bi;
                    float qx = __shfl_down_sync(0xffffffffu, vx, 4);
                    float qy = __shfl_down_sync(0xffffffffu, vy, 4);
                    if (!(r & 1) && oc < M) {
                        uint2 st;
                        st.x = pack_bf16(vx, qx);
                        st.y = pack_bf16(vy, qy);
                        *(uint2*)&outp[((size_t)n * M2 + (oc >> 1)) * HWSZ + pix0 + cb + j * 8] = st;
                    }
                }
            }
    } else {
#pragma unroll
        for (int mt = 0; mt < 2; mt++)
#pragma unroll
            for (int half = 0; half < 2; half++) {
                int oc = mbase + r0 + mt * 16 + half * 8;
                if (oc >= M) continue;
                float bi = bias ? bias[oc] : 0.f;
                size_t ob = ((size_t)n * M + oc) * HWSZ + pix0 + cb;
#pragma unroll
                for (int j = 0; j < 8; j++) {
                    float2 v = (half == 0)
                        ? make_float2(acc[mt][j].x + bi, acc[mt][j].y + bi)
                        : make_float2(acc[mt][j].z + bi, acc[mt][j].w + bi);
                    if (resid) {
                        float2 rv = *(const float2*)&resid[ob + j * 8];
                        v.x += rv.x; v.y += rv.y;
                    }
                    *(float2*)&outf[ob + j * 8] = v;
                }
            }
    }
}

// ---------------- depthwise 3x3 on packed bf16 (channel pairs) ----------------
template <int DIL>
__global__ __launch_bounds__(256) void dw3x3_p(const uint32_t* __restrict__ inp,
                                               const float* __restrict__ w,
                                               const float* __restrict__ bias,
                                               uint32_t* __restrict__ outp, int CH2) {
    size_t idx = (size_t)blockIdx.x * 256 + threadIdx.x;
    size_t tot = (size_t)NN * CH2 * 4096;
    if (idx >= tot) return;
    int q = (int)(idx & 4095);
    int nc2 = (int)(idx >> 12);
    int c2 = nc2 % CH2;
    int h = q >> 5, x4 = (q & 31) << 2;
    const uint32_t* src = inp + (size_t)nc2 * HWSZ;
    float wl[9], wh[9];
#pragma unroll
    for (int i = 0; i < 9; i++) {
        wl[i] = w[(2 * c2) * 9 + i];
        wh[i] = w[(2 * c2 + 1) * 9 + i];
    }
    float bl = bias ? bias[2 * c2] : 0.f;
    float bh = bias ? bias[2 * c2 + 1] : 0.f;
    float al[4] = {bl, bl, bl, bl}, ah[4] = {bh, bh, bh, bh};
#pragma unroll
    for (int ki = 0; ki < 3; ki++) {
        int hh = h + (ki - 1) * DIL;
        if ((unsigned)hh >= 128u) continue;
        const uint32_t* row = src + hh * WD;
        uint32_t wbuf[12];
        *(uint4*)&wbuf[0] = uz4(row + x4 - 4, x4 >= 4);
        *(uint4*)&wbuf[4] = *(const uint4*)(row + x4);
        *(uint4*)&wbuf[8] = uz4(row + x4 + 4, x4 < 124);
        float flo[12], fhi[12];
#pragma unroll
        for (int i = 0; i < 12; i++) { float2 f = upk(wbuf[i]); flo[i] = f.x; fhi[i] = f.y; }
#pragma unroll
        for (int kj = 0; kj < 3; kj++) {
            float wvl = wl[ki * 3 + kj], wvh = wh[ki * 3 + kj];
            int off = 4 + (kj - 1) * DIL;
#pragma unroll
            for (int p = 0; p < 4; p++) {
                al[p] = fmaf(flo[off + p], wvl, al[p]);
                ah[p] = fmaf(fhi[off + p], wvh, ah[p]);
            }
        }
    }
    uint4 st;
    st.x = pack_bf16(al[0], ah[0]); st.y = pack_bf16(al[1], ah[1]);
    st.z = pack_bf16(al[2], ah[2]); st.w = pack_bf16(al[3], ah[3]);
    *(uint4*)&outp[(size_t)nc2 * HWSZ + q * 4] = st;
}

// ---------------- SWSA window attention (packed bf16 in/out, tensor cores) ----------------
__global__ __launch_bounds__(256) void swsa4p(const uint32_t* __restrict__ qkvp,
                                              const float* __restrict__ rpb,
                                              uint32_t* __restrict__ outp) {
    __shared__ float qsh[4 * 64 * 17];     // Q fp32 [head][q][d] x0.25 ; reused as osh [c][68]
    __shared__ float kshB[4 * 16 * 68];    // K fp32 [d][col]
    __shared__ uint32_t vsh[4 * 32 * 17];  // V bf16x2 pixel-pairs [head][k2][d]
    __shared__ float bsh4[4 * 225];

    const int tid = threadIdx.x;
    const int lane = tid & 31, warp = tid >> 5;
    const int n = blockIdx.x >> 8;
    const int wrem = blockIdx.x & 255;
    const int wbase = ((wrem >> 4) * 8) * WD + (wrem & 15) * 8;
    const size_t nb = (size_t)n * 96 * HWSZ;

    for (int i = tid; i < 512; i += 256) {
        int c2 = i >> 4, q4 = i & 15;
        int q0 = q4 * 4;
        int goff = wbase + (q4 >> 1) * WD + (q4 & 1) * 4;
        int head = c2 >> 3;
        int d0 = (c2 & 7) * 2, d1 = d0 + 1;
        uint4 Qw = *(const uint4*)&qkvp[nb + (size_t)c2 * HWSZ + goff];
        uint4 Kw = *(const uint4*)&qkvp[nb + (size_t)(32 + c2) * HWSZ + goff];
        uint4 Vw = *(const uint4*)&qkvp[nb + (size_t)(64 + c2) * HWSZ + goff];
        const uint32_t* qw = &Qw.x;
        const uint32_t* kw = &Kw.x;
#pragma unroll
        for (int j = 0; j < 4; j++) {
            float2 fq = upk(qw[j]);
            qsh[(head * 64 + q0 + j) * 17 + d0] = fq.x * 0.25f;
            qsh[(head * 64 + q0 + j) * 17 + d1] = fq.y * 0.25f;
            float2 fk = upk(kw[j]);
            kshB[(head * 16 + d0) * 68 + q0 + j] = fk.x;
            kshB[(head * 16 + d1) * 68 + q0 + j] = fk.y;
        }
        // V repack: channel-pair words -> pixel-pair words per channel
        int k2a = q4 * 2, k2b = k2a + 1;
        vsh[(head * 32 + k2a) * 17 + d0] = (Vw.x & 0xFFFFu) | (Vw.y << 16);
        vsh[(head * 32 + k2b) * 17 + d0] = (Vw.z & 0xFFFFu) | (Vw.w << 16);
        vsh[(head * 32 + k2a) * 17 + d1] = (Vw.x >> 16) | (Vw.y & 0xFFFF0000u);
        vsh[(head * 32 + k2b) * 17 + d1] = (Vw.z >> 16) | (Vw.w & 0xFFFF0000u);
    }
    for (int i = tid; i < 900; i += 256) bsh4[(i & 3) * 225 + (i >> 2)] = rpb[i];
    __syncthreads();

    const int head = warp >> 1;
    const int qbase = (warp & 1) * 32;
    const int r = lane >> 2;
    const int l3 = lane & 3;
    const int kj2 = l3 * 2;

    // ---- QK^T (tf32) ----
    float4 S[2][8];
#pragma unroll
    for (int mt = 0; mt < 2; mt++)
#pragma unroll
        for (int nt = 0; nt < 8; nt++) S[mt][nt] = make_float4(0.f, 0.f, 0.f, 0.f);
    const float* Q = &qsh[head * 64 * 17];
    const float* K = &kshB[head * 16 * 68];
#pragma unroll
    for (int kb = 0; kb < 16; kb += 8) {
        const int kc = kb + l3;
        uint32_t a[2][4];
#pragma unroll
        for (int mt = 0; mt < 2; mt++) {
            int ar = qbase + mt * 16 + r;
            a[mt][0] = __float_as_uint(Q[ar * 17 + kc]);
            a[mt][1] = __float_as_uint(Q[(ar + 8) * 17 + kc]);
            a[mt][2] = __float_as_uint(Q[ar * 17 + kc + 4]);
            a[mt][3] = __float_as_uint(Q[(ar + 8) * 17 + kc + 4]);
        }
#pragma unroll
        for (int nt = 0; nt < 8; nt++) {
            uint32_t b0 = __float_as_uint(K[(kb + l3) * 68 + nt * 8 + r]);
            uint32_t b1 = __float_as_uint(K[(kb + 4 + l3) * 68 + nt * 8 + r]);
            mma_tf32(S[0][nt], a[0][0], a[0][1], a[0][2], a[0][3], b0, b1);
            mma_tf32(S[1][nt], a[1][0], a[1][1], a[1][2], a[1][3], b0, b1);
        }
    }

    // ---- bias + exp + relu^2 ----
    int Aq[2][2];
#pragma unroll
    for (int mt = 0; mt < 2; mt++)
#pragma unroll
        for (int rh = 0; rh < 2; rh++) {
            int q = qbase + mt * 16 + r + rh * 8;
            Aq[mt][rh] = ((q >> 3) + 7) * 15 + (q & 7) + 7;
        }
    const float* bh = &bsh4[head * 225];
    float den[2][2] = {{0.f, 0.f}, {0.f, 0.f}};
    uint32_t eb[2][8][2], ub[2][8][2];
#pragma unroll
    for (int mt = 0; mt < 2; mt++)
#pragma unroll
        for (int nt = 0; nt < 8; nt++) {
            int bc = nt * 15 + kj2;
            int i0 = Aq[mt][0] - bc;
            int i1 = Aq[mt][1] - bc;
            float4 s = S[mt][nt];
            float s0 = s.x + bh[i0], s1 = s.y + bh[i0 - 1];
            float s2 = s.z + bh[i1], s3 = s.w + bh[i1 - 1];
            float e0 = __expf(s0), e1 = __expf(s1), e2 = __expf(s2), e3 = __expf(s3);
            den[mt][0] += e0 + e1;
            den[mt][1] += e2 + e3;
            eb[mt][nt][0] = pack_bf16(e0, e1);
            eb[mt][nt][1] = pack_bf16(e2, e3);
            float u0 = fmaxf(s0, 0.f); u0 = 0.75f * u0 * u0;
            float u1 = fmaxf(s1, 0.f); u1 = 0.75f * u1 * u1;
            float u2 = fmaxf(s2, 0.f); u2 = 0.75f * u2 * u2;
            float u3 = fmaxf(s3, 0.f); u3 = 0.75f * u3 * u3;
            ub[mt][nt][0] = pack_bf16(u0, u1);
            ub[mt][nt][1] = pack_bf16(u2, u3);
        }
    uint32_t w2[2][2];
#pragma unroll
    for (int mt = 0; mt < 2; mt++)
#pragma unroll
        for (int rh = 0; rh < 2; rh++) {
            float dv = den[mt][rh];
            dv += __shfl_xor_sync(0xffffffffu, dv, 1);
            dv += __shfl_xor_sync(0xffffffffu, dv, 2);
            float wsm = 0.25f / dv;
            w2[mt][rh] = pack_bf16(wsm, wsm);
        }

    // ---- PV (bf16, C->A fragment reuse) ----
    float4 O[2][2];
#pragma unroll
    for (int mt = 0; mt < 2; mt++)
#pragma unroll
        for (int v = 0; v < 2; v++) O[mt][v] = make_float4(0.f, 0.f, 0.f, 0.f);
    const uint32_t* V = &vsh[head * 32 * 17];
#pragma unroll
    for (int mt = 0; mt < 2; mt++)
#pragma unroll
        for (int t = 0; t < 4; t++) {
            uint32_t a0 = hfma2_bf(eb[mt][2 * t][0], w2[mt][0], ub[mt][2 * t][0]);
            uint32_t a1 = hfma2_bf(eb[mt][2 * t][1], w2[mt][1], ub[mt][2 * t][1]);
            uint32_t a2 = hfma2_bf(eb[mt][2 * t + 1][0], w2[mt][0], ub[mt][2 * t + 1][0]);
            uint32_t a3 = hfma2_bf(eb[mt][2 * t + 1][1], w2[mt][1], ub[mt][2 * t + 1][1]);
#pragma unroll
            for (int v = 0; v < 2; v++) {
                uint32_t b0 = V[(t * 8 + l3) * 17 + v * 8 + r];
                uint32_t b1 = V[(t * 8 + 4 + l3) * 17 + v * 8 + r];
                mma_bf16(O[mt][v], a0, a1, a2, a3, b0, b1);
            }
        }

    // ---- stage output + packed store ----
    __syncthreads();
    float* osh = qsh;
#pragma unroll
    for (int mt = 0; mt < 2; mt++)
#pragma unroll
        for (int v = 0; v < 2; v++) {
            int qrow = qbase + mt * 16 + r;
            int c0 = head * 16 + v * 8 + kj2;
            osh[c0 * 68 + qrow] = O[mt][v].x;
            osh[(c0 + 1) * 68 + qrow] = O[mt][v].y;
            osh[c0 * 68 + qrow + 8] = O[mt][v].z;
            osh[(c0 + 1) * 68 + qrow + 8] = O[mt][v].w;
        }
    __syncthreads();
    for (int i = tid; i < 512; i += 256) {
        int c2 = i >> 4, q4 = i & 15;
        int q0 = q4 * 4;
        int goff = wbase + (q4 >> 1) * WD + (q4 & 1) * 4;
        const float* lo = &osh[(2 * c2) * 68 + q0];
        const float* hi = &osh[(2 * c2 + 1) * 68 + q0];
        uint4 st;
        st.x = pack_bf16(lo[0], hi[0]); st.y = pack_bf16(lo[1], hi[1]);
        st.z = pack_bf16(lo[2], hi[2]); st.w = pack_bf16(lo[3], hi[3]);
        *(uint4*)&outp[((size_t)n * 32 + c2) * HWSZ + goff] = st;
    }
}

// ---------------- MDTA gram partials (packed input) ----------------
__global__ __launch_bounds__(256) void mdta_gram_p(const uint32_t* __restrict__ qkvp,
                                                   float* __restrict__ part) {
    int blk = blockIdx.x;
    int seg = blk & 15;
    int nh = blk >> 4;
    int n = nh >> 2, head = nh & 3;
    int c = threadIdx.x >> 4, d = threadIdx.x & 15;
    __shared__ float qsh[16 * 129];
    __shared__ float ksh2[16 * 129];
    float acc = 0.f, qq = 0.f, kk2 = 0.f;
    const uint32_t* qb = qkvp + ((size_t)n * 96 + head * 8) * HWSZ;
    const uint32_t* kb = qkvp + ((size_t)n * 96 + 32 + head * 8) * HWSZ;
    int base0 = seg * 1024;
    for (int it = 0; it < 8; it++) {
        int base = base0 + it * 128;
        for (int i = threadIdx.x; i < 1024; i += 256) {
            int cc2 = i >> 7, j = i & 127;
            float2 fq = upk(qb[(size_t)cc2 * HWSZ + base + j]);
            qsh[(2 * cc2) * 129 + j] = fq.x;
            qsh[(2 * cc2 + 1) * 129 + j] = fq.y;
            float2 fk = upk(kb[(size_t)cc2 * HWSZ + base + j]);
            ksh2[(2 * cc2) * 129 + j] = fk.x;
            ksh2[(2 * cc2 + 1) * 129 + j] = fk.y;
        }
        __syncthreads();
#pragma unroll 8
        for (int j = 0; j < 128; j++) {
            float qv = qsh[c * 129 + j];
            float kv = ksh2[d * 129 + j];
            acc = fmaf(qv, kv, acc);
            if (d == 0) qq = fmaf(qv, qv, qq);
            if (c == 0) kk2 = fmaf(kv, kv, kk2);
        }
        __syncthreads();
    }
    float* pb = part + (size_t)blk * 288;
    pb[c * 16 + d] = acc;
    if (d == 0) pb[256 + c] = qq;
    if (c == 0) pb[272 + d] = kk2;
}

__global__ __launch_bounds__(256) void mdta_gram_reduce(const float* __restrict__ part,
                                                        const float* __restrict__ temp,
                                                        float* __restrict__ attn_out) {
    int nh = blockIdx.x;
    int n = nh >> 2, head = nh & 3;
    int tid = threadIdx.x;
    __shared__ float gram[256];
    __shared__ float qn[16], kn[16];
    float g = 0.f;
    for (int s = 0; s < 16; s++) g += part[(size_t)(nh * 16 + s) * 288 + tid];
    gram[tid] = g;
    if (tid < 16) {
        float qq = 0.f;
        for (int s = 0; s < 16; s++) qq += part[(size_t)(nh * 16 + s) * 288 + 256 + tid];
        qn[tid] = sqrtf(qq);
    } else if (tid < 32) {
        float kk = 0.f;
        for (int s = 0; s < 16; s++) kk += part[(size_t)(nh * 16 + s) * 288 + 272 + (tid - 16)];
        kn[tid - 16] = sqrtf(kk);
    }
    __syncthreads();
    if (tid < 16) {
        int r = tid;
        float tp = temp[head];
        float iq = 1.f / fmaxf(qn[r], 1e-12f);
        float rowv[16];
        float mx = -1e30f;
#pragma unroll
        for (int j = 0; j < 16; j++) {
            float a = gram[r * 16 + j] * iq / fmaxf(kn[j], 1e-12f) * tp;
            rowv[j] = a;
            mx = fmaxf(mx, a);
        }
        float den = 0.f;
#pragma unroll
        for (int j = 0; j < 16; j++) { float e = __expf(rowv[j] - mx); rowv[j] = e; den += e; }
        float inv = 1.f / den;
#pragma unroll
        for (int j = 0; j < 16; j++)
            attn_out[(((size_t)n * NHEADS + head) * 16 + r) * 16 + j] = rowv[j] * inv;
    }
}

// ---------------- MDTA: out = attn @ v (packed in/out) ----------------
__global__ __launch_bounds__(256) void mdta_out_p(const uint32_t* __restrict__ qkvp,
                                                  const float* __restrict__ attn,
                                                  uint32_t* __restrict__ outp) {
    __shared__ float ash[NHEADS * 256];
    int n = blockIdx.y;
    for (int i = threadIdx.x; i < NHEADS * 256; i += 256)
        ash[i] = attn[(size_t)n * NHEADS * 256 + i];
    __syncthreads();
    int hw = (blockIdx.x * 256 + threadIdx.x) * 4;
#pragma unroll
    for (int head = 0; head < NHEADS; head++) {
        float vv[16][4];
        const uint32_t* vb = qkvp + ((size_t)n * 96 + 64 + head * 8) * HWSZ + hw;
#pragma unroll
        for (int d2 = 0; d2 < 8; d2++) {
            uint4 wv = *(const uint4*)(vb + (size_t)d2 * HWSZ);
            const uint32_t* ws = &wv.x;
#pragma unroll
            for (int p = 0; p < 4; p++) {
                float2 f = upk(ws[p]);
                vv[2 * d2][p] = f.x;
                vv[2 * d2 + 1][p] = f.y;
            }
        }
#pragma unroll
        for (int c2 = 0; c2 < 8; c2++) {
            float slo[4] = {0.f, 0.f, 0.f, 0.f}, shi[4] = {0.f, 0.f, 0.f, 0.f};
            const float* alo = &ash[(head * 16 + 2 * c2) * 16];
            const float* ahi = &ash[(head * 16 + 2 * c2 + 1) * 16];
#pragma unroll
            for (int d = 0; d < 16; d++) {
                float wl = alo[d], wh = ahi[d];
#pragma unroll
                for (int p = 0; p < 4; p++) {
                    slo[p] = fmaf(wl, vv[d][p], slo[p]);
                    shi[p] = fmaf(wh, vv[d][p], shi[p]);
                }
            }
            uint4 st;
            st.x = pack_bf16(slo[0], shi[0]); st.y = pack_bf16(slo[1], shi[1]);
            st.z = pack_bf16(slo[2], shi[2]); st.w = pack_bf16(slo[3], shi[3]);
            *(uint4*)&outp[((size_t)n * 32 + head * 8 + c2) * HWSZ + hw] = st;
        }
    }
}

// ---------------- GDFN depthwise + gelu gate (packed in/out) ----------------
__global__ __launch_bounds__(256) void gdfn_p(const uint32_t* __restrict__ inp,
                                              const float* __restrict__ w1,
                                              const float* __restrict__ b1,
                                              const float* __restrict__ w2,
                                              const float* __restrict__ b2,
                                              uint32_t* __restrict__ outp) {
    size_t idx = (size_t)blockIdx.x * 256 + threadIdx.x;
    size_t tot = (size_t)NN * 85 * 4096;
    if (idx >= tot) return;
    int q = (int)(idx & 4095);
    int nc2 = (int)(idx >> 12);
    int c2 = nc2 % 85, n = nc2 / 85;
    int h = q >> 5, x4 = (q & 31) << 2;
    const uint32_t* s1 = inp + ((size_t)n * 170 + c2) * HWSZ;       // x1 channels 2c2, 2c2+1
    const uint32_t* s2 = inp + ((size_t)n * 170 + 85 + c2) * HWSZ;  // x2 channels 170+2c2, +1
    float w1l[9], w1h[9], w2l[9], w2h[9];
#pragma unroll
    for (int i = 0; i < 9; i++) {
        w1l[i] = w1[(2 * c2) * 9 + i]; w1h[i] = w1[(2 * c2 + 1) * 9 + i];
        w2l[i] = w2[(2 * c2) * 9 + i]; w2h[i] = w2[(2 * c2 + 1) * 9 + i];
    }
    float bal = b1[2 * c2], bah = b1[2 * c2 + 1];
    float bbl = b2[2 * c2], bbh = b2[2 * c2 + 1];
    float al[4] = {bal, bal, bal, bal}, ah[4] = {bah, bah, bah, bah};
    float bl[4] = {bbl, bbl, bbl, bbl}, bh[4] = {bbh, bbh, bbh, bbh};
#pragma unroll
    for (int ki = 0; ki < 3; ki++) {
        int hh = h + (ki - 1);
        if ((unsigned)hh >= 128u) continue;
        const uint32_t* r1 = s1 + hh * WD;
        const uint32_t* r2 = s2 + hh * WD;
        uint32_t wb1[12], wb2[12];
        *(uint4*)&wb1[0] = uz4(r1 + x4 - 4, x4 >= 4);
        *(uint4*)&wb1[4] = *(const uint4*)(r1 + x4);
        *(uint4*)&wb1[8] = uz4(r1 + x4 + 4, x4 < 124);
        *(uint4*)&wb2[0] = uz4(r2 + x4 - 4, x4 >= 4);
        *(uint4*)&wb2[4] = *(const uint4*)(r2 + x4);
        *(uint4*)&wb2[8] = uz4(r2 + x4 + 4, x4 < 124);
        float f1l[12], f1h[12], f2l[12], f2h[12];
#pragma unroll
        for (int i = 0; i < 12; i++) {
            float2 fa = upk(wb1[i]); f1l[i] = fa.x; f1h[i] = fa.y;
            float2 fb = upk(wb2[i]); f2l[i] = fb.x; f2h[i] = fb.y;
        }
#pragma unroll
        for (int kj = 0; kj < 3; kj++) {
            int off = 4 + (kj - 1);
            float v1l = w1l[ki * 3 + kj], v1h = w1h[ki * 3 + kj];
            float v2l = w2l[ki * 3 + kj], v2h = w2h[ki * 3 + kj];
#pragma unroll
            for (int p = 0; p < 4; p++) {
                al[p] = fmaf(f1l[off + p], v1l, al[p]);
                ah[p] = fmaf(f1h[off + p], v1h, ah[p]);
                bl[p] = fmaf(f2l[off + p], v2l, bl[p]);
                bh[p] = fmaf(f2h[off + p], v2h, bh[p]);
            }
        }
    }
    uint4 st;
    uint32_t* sp = &st.x;
#pragma unroll
    for (int p = 0; p < 4; p++) {
        float gl = 0.5f * al[p] * (1.f + erff(al[p] * 0.70710678118654752f));
        float gh = 0.5f * ah[p] * (1.f + erff(ah[p] * 0.70710678118654752f));
        sp[p] = pack_bf16(gl * bl[p], gh * bh[p]);
    }
    *(uint4*)&outp[(size_t)nc2 * HWSZ + q * 4] = st;
}

// ---------------- launch ----------------
extern "C" void kernel_launch(void* const* d_in, const int* in_sizes, int n_in,
                              void* d_out, int out_size) {
    const float* x       = (const float*)d_in[0];
    const float* norm_w  = (const float*)d_in[1];
    const float* norm_b  = (const float*)d_in[2];
    const float* s_cin_w = (const float*)d_in[3];
    const float* s_cin_b = (const float*)d_in[4];
    const float* s_dw_w  = (const float*)d_in[5];
    const float* s_dw_b  = (const float*)d_in[6];
    const float* s_rpb   = (const float*)d_in[7];
    const float* s_cout_w= (const float*)d_in[8];
    const float* s_cout_b= (const float*)d_in[9];
    const float* m_qkv_w = (const float*)d_in[10];
    const float* m_dw_w  = (const float*)d_in[11];
    const float* m_proj_w= (const float*)d_in[12];
    const float* m_temp  = (const float*)d_in[13];
    const float* g_in_w  = (const float*)d_in[14];
    const float* g_in_b  = (const float*)d_in[15];
    const float* g_d1_w  = (const float*)d_in[16];
    const float* g_d1_b  = (const float*)d_in[17];
    const float* g_d2_w  = (const float*)d_in[18];
    const float* g_d2_b  = (const float*)d_in[19];
    const float* g_out_w = (const float*)d_in[20];
    const float* g_out_b = (const float*)d_in[21];
    float* xo = (float*)d_out;

    uint32_t *lnp, *bufAp, *bufBp, *wp;
    float *attn, *part;
    cudaGetSymbolAddress((void**)&lnp, g_lnp);
    cudaGetSymbolAddress((void**)&bufAp, g_bufAp);
    cudaGetSymbolAddress((void**)&bufBp, g_bufBp);
    cudaGetSymbolAddress((void**)&attn, g_attn);
    cudaGetSymbolAddress((void**)&part, g_part);
    cudaGetSymbolAddress((void**)&wp, g_wp);

    const int ln_blocks = NN * HWSZ / 256;

    // ---- pack all GEMM weights to bf16x2 ----
    wpack_kernel<3><<<(192 * 96 + 255) / 256, 256>>>(s_cin_w, wp + WP_SCIN, 192, 32, 96);
    wpack_kernel<3><<<(64 * 96 + 255) / 256, 256>>>(s_cout_w, wp + WP_SCOUT, 64, 32, 96);
    wpack_kernel<1><<<(192 * 32 + 255) / 256, 256>>>(m_qkv_w, wp + WP_MQKV, 192, 32, 32);
    wpack_kernel<1><<<(64 * 32 + 255) / 256, 256>>>(m_proj_w, wp + WP_MPROJ, 64, 32, 32);
    wpack_kernel<1><<<(340 * 32 + 255) / 256, 256>>>(g_in_w, wp + WP_GIN, 340, 32, 32);
    wpack_kernel<1><<<(64 * 88 + 255) / 256, 256>>>(g_out_w, wp + WP_GOUT, 64, 85, 88);

    // ===== SWSA branch =====
    ln_p<<<ln_blocks, 256>>>(x, norm_w, norm_b, lnp);
    pconv5<32, 3, 128, true><<<dim3(128, 2, NN), 256>>>(lnp, wp + WP_SCIN, s_cin_b,
                                                        nullptr, nullptr, bufBp, C3);
    dw3x3_p<1><<<(NN * 96 * 4096 + 255) / 256, 256>>>(bufBp, s_dw_w, s_dw_b, bufAp, 96);
    swsa4p<<<NN * 256, 256>>>(bufAp, s_rpb, lnp);
    pconv5<32, 3, 64, false><<<dim3(64, 1, NN), 256>>>(lnp, wp + WP_SCOUT, s_cout_b,
                                                       x, xo, nullptr, CCH);

    // ===== MDTA branch =====
    ln_p<<<ln_blocks, 256>>>(xo, norm_w, norm_b, lnp);
    pconv5<32, 1, 128, true><<<dim3(128, 2, NN), 256>>>(lnp, wp + WP_MQKV, nullptr,
                                                        nullptr, nullptr, bufBp, C3);
    dw3x3_p<2><<<(NN * 96 * 4096 + 255) / 256, 256>>>(bufBp, m_dw_w, nullptr, bufAp, 96);
    mdta_gram_p<<<512, 256>>>(bufAp, part);
    mdta_gram_reduce<<<32, 256>>>(part, m_temp, attn);
    mdta_out_p<<<dim3(16, NN), 256>>>(bufAp, attn, lnp);
    pconv5<32, 1, 64, false><<<dim3(64, 1, NN), 256>>>(lnp, wp + WP_MPROJ, nullptr,
                                                       xo, xo, nullptr, CCH);

    // ===== GDFN branch =====
    ln_p<<<ln_blocks, 256>>>(xo, norm_w, norm_b, lnp);
    pconv5<32, 1, 128, true><<<dim3(128, 3, NN), 256>>>(lnp, wp + WP_GIN, g_in_b,
                                                        nullptr, nullptr, bufAp, HID2);
    gdfn_p<<<(NN * 85 * 4096 + 255) / 256, 256>>>(bufAp, g_d1_w, g_d1_b, g_d2_w, g_d2_b, bufBp);
    pconv5<85, 1, 64, false><<<dim3(64, 1, NN), 256>>>(bufBp, wp + WP_GOUT, g_out_b,
                                                       xo, xo, nullptr, CCH);
}